// round 14
// baseline (speedup 1.0000x reference)
#include <cuda_runtime.h>
#include <cuda_bf16.h>
#include <math_constants.h>
#include <cstdint>

#define NN 50000
#define NE 800000
#define FIN 512
#define FH 128
#define FO 40

#define NB_SCAN ((NN + 255) / 256)   // 196

// ---------------- scratch (device globals: no allocation allowed) ----------
__device__ float g_dinv[NN];
__device__ int   g_cnt[NN];
__device__ int   g_ptr[NN];
__device__ int   g_cur[NN];
__device__ int   g_bsum[256];
__device__ uint2 g_edges[NE];              // packed (src, norm) sorted by dst
__device__ float g_h1[NN * FH];
__device__ float g_h2[NN * FO];
__device__ __nv_bfloat16 g_r1h[NN * FH];   // relu(a1+b1) hi
__device__ __nv_bfloat16 g_r1l[NN * FH];   // relu(a1+b1) lo
__device__ __nv_bfloat16 g_W1t_hi[FH * FIN];   // W1^T hi, [n][k]
__device__ __nv_bfloat16 g_W1t_lo[FH * FIN];   // W1^T lo
__device__ __nv_bfloat16 g_W2t_hi[FO * FH];    // W2^T hi, [n][k]
__device__ __nv_bfloat16 g_W2t_lo[FO * FH];    // W2^T lo

// ---- side stream + events, created once at program init -------------------
struct SideStream {
    cudaStream_t s2;
    cudaEvent_t ev_fork, ev_join;
    SideStream() {
        cudaStreamCreateWithFlags(&s2, cudaStreamNonBlocking);
        cudaEventCreateWithFlags(&ev_fork, cudaEventDisableTiming);
        cudaEventCreateWithFlags(&ev_join, cudaEventDisableTiming);
    }
};
static SideStream g_ss;

// ================= warp-MMA helpers (arch-neutral PTX, sm_80+) =============
__device__ __forceinline__ uint32_t smem_to_u32(const void* p) {
    uint32_t a;
    asm("{ .reg .u64 t; cvta.to.shared.u64 t, %1; cvt.u32.u64 %0, t; }"
        : "=r"(a) : "l"(p));
    return a;
}

__device__ __forceinline__ void ldsm_x4(uint32_t* r, uint32_t addr) {
    asm volatile("ldmatrix.sync.aligned.m8n8.x4.shared.b16 {%0,%1,%2,%3}, [%4];"
        : "=r"(r[0]), "=r"(r[1]), "=r"(r[2]), "=r"(r[3]) : "r"(addr));
}

__device__ __forceinline__ void ldsm_x2(uint32_t* r, uint32_t addr) {
    asm volatile("ldmatrix.sync.aligned.m8n8.x2.shared.b16 {%0,%1}, [%2];"
        : "=r"(r[0]), "=r"(r[1]) : "r"(addr));
}

__device__ __forceinline__ void mma16816(float* d, const uint32_t* a,
                                         const uint32_t* b) {
    asm volatile("mma.sync.aligned.m16n8k16.row.col.f32.bf16.bf16.f32 "
        "{%0,%1,%2,%3}, {%4,%5,%6,%7}, {%8,%9}, {%0,%1,%2,%3};"
        : "+f"(d[0]), "+f"(d[1]), "+f"(d[2]), "+f"(d[3])
        : "r"(a[0]), "r"(a[1]), "r"(a[2]), "r"(a[3]), "r"(b[0]), "r"(b[1]));
}

#define CP_ASYNC16(dst, src) \
    asm volatile("cp.async.cg.shared.global [%0], [%1], 16;" \
        :: "r"(dst), "l"(src) : "memory")
#define CP_COMMIT() asm volatile("cp.async.commit_group;" ::: "memory")

#define SWZ(off) ((off) ^ (((off) >> 3) & 0x70))

// ---------------- fused init: dinv/cnt reset + W1 & W2 splits --------------
__global__ void k_prep(const float* __restrict__ W1,
                       const float* __restrict__ W2) {
    int i = blockIdx.x * blockDim.x + threadIdx.x;
    if (i < NN) { g_dinv[i] = 1.0f; g_cnt[i] = 0; }
    if (i < FIN * FH) {
        int k = i >> 7, n = i & 127;
        float v = W1[i];
        __nv_bfloat16 h = __float2bfloat16(v);
        g_W1t_hi[n * FIN + k] = h;
        g_W1t_lo[n * FIN + k] = __float2bfloat16(v - __bfloat162float(h));
    }
    if (i < FH * FO) {
        int k = i / FO, n = i % FO;
        float v = W2[i];
        __nv_bfloat16 h = __float2bfloat16(v);
        g_W2t_hi[n * FH + k] = h;
        g_W2t_lo[n * FH + k] = __float2bfloat16(v - __bfloat162float(h));
    }
}

__global__ void k_deg_hist(const int* __restrict__ ei, const float* __restrict__ w) {
    int e = blockIdx.x * blockDim.x + threadIdx.x;
    if (e < NE) {
        int c = ei[NE + e];
        atomicAdd(&g_dinv[c], w[e]);
        atomicAdd(&g_cnt[c], 1);
    }
}

// ---------------- 3-kernel exclusive scan (scan1 fuses dinv finalize) ------
__global__ void k_scan1() {
    __shared__ int sh[256];
    int tid = threadIdx.x;
    int i = blockIdx.x * 256 + tid;
    int v = (i < NN) ? g_cnt[i] : 0;
    if (i < NN) g_dinv[i] = rsqrtf(g_dinv[i]);   // deg >= 1 always
    sh[tid] = v;
    __syncthreads();
    #pragma unroll
    for (int o = 1; o < 256; o <<= 1) {
        int t = (tid >= o) ? sh[tid - o] : 0;
        __syncthreads();
        sh[tid] += t;
        __syncthreads();
    }
    if (i < NN) g_ptr[i] = sh[tid] - v;
    if (tid == 255) g_bsum[blockIdx.x] = sh[255];
}

__global__ void k_scan2() {
    __shared__ int sh[256];
    int tid = threadIdx.x;
    int v = (tid < NB_SCAN) ? g_bsum[tid] : 0;
    sh[tid] = v;
    __syncthreads();
    #pragma unroll
    for (int o = 1; o < 256; o <<= 1) {
        int t = (tid >= o) ? sh[tid - o] : 0;
        __syncthreads();
        sh[tid] += t;
        __syncthreads();
    }
    if (tid < NB_SCAN) g_bsum[tid] = sh[tid] - v;
}

__global__ void k_scan3() {
    int i = blockIdx.x * blockDim.x + threadIdx.x;
    if (i < NN) {
        int p = g_ptr[i] + g_bsum[i >> 8];
        g_ptr[i] = p;
        g_cur[i] = p;
    }
}

__global__ void k_fill(const int* __restrict__ ei, const float* __restrict__ w) {
    int e = blockIdx.x * blockDim.x + threadIdx.x;
    if (e < NE) {
        int r = ei[e];
        int c = ei[NE + e];
        float nrm = g_dinv[r] * w[e] * g_dinv[c];
        int pos = atomicAdd(&g_cur[c], 1);
        g_edges[pos] = make_uint2((unsigned)r, __float_as_uint(nrm));
    }
}

// ---------------- GEMM1 (mma.sync 3xBF16, pipelined): h1 = x @ W1 ----------
// __launch_bounds__(256, 2): cap regs at 128 so two 96KB-smem CTAs co-reside
// per SM (192KB < 228KB), letting one CTA's MMA phase cover the other's
// load/convert phase.
#define OFF_AH 0
#define OFF_AL 16384
#define OFF_B  32768
#define GEMM1_SMEM 98304

__global__ void __launch_bounds__(256, 2) k_gemm1_mma(const float* __restrict__ A) {
    extern __shared__ char smem[];
    uint32_t sb = smem_to_u32(smem);
    int tid = threadIdx.x;
    int wid = tid >> 5;
    int lane = tid & 31;
    int row0 = blockIdx.x * 128;
    int warp_m = (wid & 3) * 32;
    int warp_n = (wid >> 2) * 64;

    float acc[2][8][4] = {};
    float4 areg[8];

    {
        uint32_t bb = sb + OFF_B;
        #pragma unroll
        for (int i = 0; i < 4; i++) {
            int slot = tid + i * 256;
            int r  = slot >> 3;
            int c8 = slot & 7;
            size_t src = (size_t)r * FIN + c8 * 8;
            uint32_t off = SWZ((uint32_t)(r * 128 + c8 * 16));
            CP_ASYNC16(bb + off,          (const void*)&g_W1t_hi[src]);
            CP_ASYNC16(bb + 16384 + off,  (const void*)&g_W1t_lo[src]);
        }
        CP_COMMIT();
        #pragma unroll
        for (int i = 0; i < 8; i++) {
            int slot = tid + i * 256;
            int r  = slot >> 4;
            int c4 = slot & 15;
            int gr = row0 + r;
            areg[i] = make_float4(0.f, 0.f, 0.f, 0.f);
            if (gr < NN) areg[i] = *(const float4*)&A[(size_t)gr * FIN + c4 * 4];
        }
    }

    for (int c = 0; c < 8; c++) {
        #pragma unroll
        for (int i = 0; i < 8; i++) {
            int slot = tid + i * 256;
            int r  = slot >> 4;
            int c4 = slot & 15;
            float4 v = areg[i];
            __nv_bfloat162 h01 = __floats2bfloat162_rn(v.x, v.y);
            __nv_bfloat162 h23 = __floats2bfloat162_rn(v.z, v.w);
            float2 hf01 = __bfloat1622float2(h01);
            float2 hf23 = __bfloat1622float2(h23);
            __nv_bfloat162 l01 = __floats2bfloat162_rn(v.x - hf01.x, v.y - hf01.y);
            __nv_bfloat162 l23 = __floats2bfloat162_rn(v.z - hf23.x, v.w - hf23.y);
            uint32_t off = SWZ((uint32_t)(r * 128 + c4 * 8));
            *(uint2*)(smem + OFF_AH + off) =
                make_uint2(*(uint32_t*)&h01, *(uint32_t*)&h23);
            *(uint2*)(smem + OFF_AL + off) =
                make_uint2(*(uint32_t*)&l01, *(uint32_t*)&l23);
        }

        if (c < 7) {
            int k1 = (c + 1) * 64;
            uint32_t bb = sb + OFF_B + ((c + 1) & 1) * 32768;
            #pragma unroll
            for (int i = 0; i < 4; i++) {
                int slot = tid + i * 256;
                int r  = slot >> 3;
                int c8 = slot & 7;
                size_t src = (size_t)r * FIN + k1 + c8 * 8;
                uint32_t off = SWZ((uint32_t)(r * 128 + c8 * 16));
                CP_ASYNC16(bb + off,         (const void*)&g_W1t_hi[src]);
                CP_ASYNC16(bb + 16384 + off, (const void*)&g_W1t_lo[src]);
            }
            CP_COMMIT();
            #pragma unroll
            for (int i = 0; i < 8; i++) {
                int slot = tid + i * 256;
                int r  = slot >> 4;
                int c4 = slot & 15;
                int gr = row0 + r;
                areg[i] = make_float4(0.f, 0.f, 0.f, 0.f);
                if (gr < NN)
                    areg[i] = *(const float4*)&A[(size_t)gr * FIN + k1 + c4 * 4];
            }
            asm volatile("cp.async.wait_group 1;" ::: "memory");
        } else {
            asm volatile("cp.async.wait_group 0;" ::: "memory");
        }
        __syncthreads();

        uint32_t offBH = (uint32_t)OFF_B + (c & 1) * 32768u;
        uint32_t offBL = offBH + 16384u;
        #pragma unroll
        for (int pass = 0; pass < 3; pass++) {
            uint32_t offA = (pass == 2) ? (uint32_t)OFF_AL : (uint32_t)OFF_AH;
            uint32_t offB = (pass == 1) ? offBL : offBH;
            #pragma unroll
            for (int ks = 0; ks < 4; ks++) {
                int t = lane >> 3;
                uint32_t afrag[2][4];
                #pragma unroll
                for (int mt = 0; mt < 2; mt++) {
                    int r  = warp_m + mt * 16 + ((t & 1) << 3) + (lane & 7);
                    int kk = ks * 16 + ((t >> 1) << 3);
                    ldsm_x4(afrag[mt], sb + offA + SWZ((uint32_t)(r * 128 + kk * 2)));
                }
                uint32_t bfrag[8][2];
                #pragma unroll
                for (int nt2 = 0; nt2 < 4; nt2++) {
                    int n  = warp_n + nt2 * 16 + ((t >> 1) << 3) + (lane & 7);
                    int kk = ks * 16 + ((t & 1) << 3);
                    uint32_t tmp[4];
                    ldsm_x4(tmp, sb + offB + SWZ((uint32_t)(n * 128 + kk * 2)));
                    bfrag[nt2 * 2][0]     = tmp[0];
                    bfrag[nt2 * 2][1]     = tmp[1];
                    bfrag[nt2 * 2 + 1][0] = tmp[2];
                    bfrag[nt2 * 2 + 1][1] = tmp[3];
                }
                #pragma unroll
                for (int mt = 0; mt < 2; mt++)
                    #pragma unroll
                    for (int nt = 0; nt < 8; nt++)
                        mma16816(acc[mt][nt], afrag[mt], bfrag[nt]);
            }
        }
        __syncthreads();
    }

    #pragma unroll
    for (int mt = 0; mt < 2; mt++) {
        int m0 = row0 + warp_m + mt * 16 + (lane >> 2);
        #pragma unroll
        for (int nt = 0; nt < 8; nt++) {
            int n = warp_n + nt * 8 + (lane & 3) * 2;
            if (m0 < NN)
                *(float2*)&g_h1[(size_t)m0 * FH + n] =
                    make_float2(acc[mt][nt][0], acc[mt][nt][1]);
            if (m0 + 8 < NN)
                *(float2*)&g_h1[(size_t)(m0 + 8) * FH + n] =
                    make_float2(acc[mt][nt][2], acc[mt][nt][3]);
        }
    }
}

// ------- layer-1 gather + bias + relu + bf16 hi/lo split (fused) ----------
// warp-per-node: maximal memory-level parallelism for the irregular gather.
__global__ void __launch_bounds__(256) k_gather1(const float* __restrict__ b1) {
    int node = (blockIdx.x * blockDim.x + threadIdx.x) >> 5;
    int lane = threadIdx.x & 31;
    if (node >= NN) return;

    int start = g_ptr[node];
    int cnt   = g_cnt[node];
    float s = g_dinv[node];
    s *= s;

    float4 acc = *(const float4*)&g_h1[(size_t)node * FH + lane * 4];
    acc.x *= s; acc.y *= s; acc.z *= s; acc.w *= s;

    int i = 0;
    for (; i + 4 <= cnt; i += 4) {
        uint2 e0 = g_edges[start + i];
        uint2 e1 = g_edges[start + i + 1];
        uint2 e2 = g_edges[start + i + 2];
        uint2 e3 = g_edges[start + i + 3];
        float n0 = __uint_as_float(e0.y);
        float n1 = __uint_as_float(e1.y);
        float n2 = __uint_as_float(e2.y);
        float n3 = __uint_as_float(e3.y);
        float4 v0 = *(const float4*)&g_h1[(size_t)e0.x * FH + lane * 4];
        float4 v1 = *(const float4*)&g_h1[(size_t)e1.x * FH + lane * 4];
        float4 v2 = *(const float4*)&g_h1[(size_t)e2.x * FH + lane * 4];
        float4 v3 = *(const float4*)&g_h1[(size_t)e3.x * FH + lane * 4];
        acc.x += v0.x * n0 + v1.x * n1 + v2.x * n2 + v3.x * n3;
        acc.y += v0.y * n0 + v1.y * n1 + v2.y * n2 + v3.y * n3;
        acc.z += v0.z * n0 + v1.z * n1 + v2.z * n2 + v3.z * n3;
        acc.w += v0.w * n0 + v1.w * n1 + v2.w * n2 + v3.w * n3;
    }
    for (; i < cnt; i++) {
        uint2 e0 = g_edges[start + i];
        float n0 = __uint_as_float(e0.y);
        float4 v0 = *(const float4*)&g_h1[(size_t)e0.x * FH + lane * 4];
        acc.x += v0.x * n0;
        acc.y += v0.y * n0;
        acc.z += v0.z * n0;
        acc.w += v0.w * n0;
    }

    float4 bv = *(const float4*)&b1[lane * 4];
    acc.x = fmaxf(acc.x + bv.x, 0.f);
    acc.y = fmaxf(acc.y + bv.y, 0.f);
    acc.z = fmaxf(acc.z + bv.z, 0.f);
    acc.w = fmaxf(acc.w + bv.w, 0.f);
    __nv_bfloat162 h01 = __floats2bfloat162_rn(acc.x, acc.y);
    __nv_bfloat162 h23 = __floats2bfloat162_rn(acc.z, acc.w);
    float2 hf01 = __bfloat1622float2(h01);
    float2 hf23 = __bfloat1622float2(h23);
    __nv_bfloat162 l01 = __floats2bfloat162_rn(acc.x - hf01.x, acc.y - hf01.y);
    __nv_bfloat162 l23 = __floats2bfloat162_rn(acc.z - hf23.x, acc.w - hf23.y);
    size_t dst = (size_t)node * FH + lane * 4;
    *(uint2*)&g_r1h[dst] = make_uint2(*(uint32_t*)&h01, *(uint32_t*)&h23);
    *(uint2*)&g_r1l[dst] = make_uint2(*(uint32_t*)&l01, *(uint32_t*)&l23);
}

// ---------------- GEMM2 (mma.sync 3xBF16): h2 = r1 @ W2 --------------------
#define G2_AH 0
#define G2_AL 32768
#define G2_BH 65536
#define G2_BL 75776
#define GEMM2_SMEM 86016

__global__ void __launch_bounds__(128) k_gemm2_mma() {
    extern __shared__ char smem[];
    uint32_t sb = smem_to_u32(smem);
    int tid = threadIdx.x;
    int wid = tid >> 5;
    int lane = tid & 31;
    int row0 = blockIdx.x * 128;

    #pragma unroll
    for (int i = 0; i < 16; i++) {
        int slot = tid + i * 128;
        int r   = slot >> 4;
        int c16 = slot & 15;
        int ch  = c16 >> 3;
        int c8  = c16 & 7;
        int gr  = row0 + r;
        uint4 vh = make_uint4(0u, 0u, 0u, 0u), vl = vh;
        if (gr < NN) {
            size_t src = (size_t)gr * FH + ch * 64 + c8 * 8;
            vh = *(const uint4*)&g_r1h[src];
            vl = *(const uint4*)&g_r1l[src];
        }
        uint32_t off = SWZ((uint32_t)(r * 128 + c8 * 16));
        *(uint4*)(smem + G2_AH + ch * 16384 + off) = vh;
        *(uint4*)(smem + G2_AL + ch * 16384 + off) = vl;
    }
    for (int slot = tid; slot < FO * 16; slot += 128) {
        int r   = slot >> 4;
        int c16 = slot & 15;
        int ch  = c16 >> 3;
        int c8  = c16 & 7;
        size_t src = (size_t)r * FH + ch * 64 + c8 * 8;
        uint4 vh = *(const uint4*)&g_W2t_hi[src];
        uint4 vl = *(const uint4*)&g_W2t_lo[src];
        uint32_t off = SWZ((uint32_t)(r * 128 + c8 * 16));
        *(uint4*)(smem + G2_BH + ch * 5120 + off) = vh;
        *(uint4*)(smem + G2_BL + ch * 5120 + off) = vl;
    }
    __syncthreads();

    float acc[2][5][4] = {};
    int warp_m = wid * 32;
    int t = lane >> 3;

    #pragma unroll
    for (int pass = 0; pass < 3; pass++) {
        uint32_t baseA = (pass == 2) ? (uint32_t)G2_AL : (uint32_t)G2_AH;
        uint32_t baseB = (pass == 1) ? (uint32_t)G2_BL : (uint32_t)G2_BH;
        #pragma unroll
        for (int ch = 0; ch < 2; ch++) {
            uint32_t offA = baseA + ch * 16384u;
            uint32_t offB = baseB + ch * 5120u;
            #pragma unroll
            for (int ks = 0; ks < 4; ks++) {
                uint32_t afrag[2][4];
                #pragma unroll
                for (int mt = 0; mt < 2; mt++) {
                    int r  = warp_m + mt * 16 + ((t & 1) << 3) + (lane & 7);
                    int kk = ks * 16 + ((t >> 1) << 3);
                    ldsm_x4(afrag[mt], sb + offA + SWZ((uint32_t)(r * 128 + kk * 2)));
                }
                uint32_t bfrag[5][2];
                #pragma unroll
                for (int g = 0; g < 2; g++) {
                    int n  = g * 16 + ((t >> 1) << 3) + (lane & 7);
                    int kk = ks * 16 + ((t & 1) << 3);
                    uint32_t tmp[4];
                    ldsm_x4(tmp, sb + offB + SWZ((uint32_t)(n * 128 + kk * 2)));
                    bfrag[g * 2][0]     = tmp[0];
                    bfrag[g * 2][1]     = tmp[1];
                    bfrag[g * 2 + 1][0] = tmp[2];
                    bfrag[g * 2 + 1][1] = tmp[3];
                }
                {
                    int l  = lane & 15;
                    int n  = 32 + (l & 7);
                    int kk = ks * 16 + ((l >> 3) << 3);
                    uint32_t tmp2[2];
                    ldsm_x2(tmp2, sb + offB + SWZ((uint32_t)(n * 128 + kk * 2)));
                    bfrag[4][0] = tmp2[0];
                    bfrag[4][1] = tmp2[1];
                }
                #pragma unroll
                for (int mt = 0; mt < 2; mt++)
                    #pragma unroll
                    for (int nt = 0; nt < 5; nt++)
                        mma16816(acc[mt][nt], afrag[mt], bfrag[nt]);
            }
        }
    }

    #pragma unroll
    for (int mt = 0; mt < 2; mt++) {
        int m0 = row0 + warp_m + mt * 16 + (lane >> 2);
        #pragma unroll
        for (int nt = 0; nt < 5; nt++) {
            int n = nt * 8 + (lane & 3) * 2;
            if (m0 < NN)
                *(float2*)&g_h2[(size_t)m0 * FO + n] =
                    make_float2(acc[mt][nt][0], acc[mt][nt][1]);
            if (m0 + 8 < NN)
                *(float2*)&g_h2[(size_t)(m0 + 8) * FO + n] =
                    make_float2(acc[mt][nt][2], acc[mt][nt][3]);
        }
    }
}

// ---------------- layer-2 gather + b2 + log_softmax ----------------
__global__ void __launch_bounds__(256) k_gather2_softmax(
        const float* __restrict__ b2, float* __restrict__ out) {
    int node = (blockIdx.x * blockDim.x + threadIdx.x) >> 5;
    int lane = threadIdx.x & 31;
    if (node >= NN) return;

    int start = g_ptr[node];
    int cnt   = g_cnt[node];
    float s = g_dinv[node];
    s *= s;

    bool p0 = (lane < FO);
    bool p1 = (lane + 32 < FO);

    const float* self = &g_h2[(size_t)node * FO];
    float acc0 = p0 ? self[lane] * s : 0.f;
    float acc1 = p1 ? self[lane + 32] * s : 0.f;

    int i = 0;
    for (; i + 2 <= cnt; i += 2) {
        uint2 e0 = g_edges[start + i];
        uint2 e1 = g_edges[start + i + 1];
        float n0 = __uint_as_float(e0.y);
        float n1 = __uint_as_float(e1.y);
        const float* h0 = &g_h2[(size_t)e0.x * FO];
        const float* h1p = &g_h2[(size_t)e1.x * FO];
        if (p0) acc0 += h0[lane] * n0 + h1p[lane] * n1;
        if (p1) acc1 += h0[lane + 32] * n0 + h1p[lane + 32] * n1;
    }
    if (i < cnt) {
        uint2 e = g_edges[start + i];
        float nrm = __uint_as_float(e.y);
        const float* hr = &g_h2[(size_t)e.x * FO];
        if (p0) acc0 += hr[lane] * nrm;
        if (p1) acc1 += hr[lane + 32] * nrm;
    }

    float v0 = p0 ? acc0 + b2[lane] : -CUDART_INF_F;
    float v1 = p1 ? acc1 + b2[lane + 32] : -CUDART_INF_F;

    float m = fmaxf(v0, v1);
    #pragma unroll
    for (int o = 16; o; o >>= 1) m = fmaxf(m, __shfl_xor_sync(0xffffffffu, m, o));

    float sum = (p0 ? expf(v0 - m) : 0.f) + (p1 ? expf(v1 - m) : 0.f);
    #pragma unroll
    for (int o = 16; o; o >>= 1) sum += __shfl_xor_sync(0xffffffffu, sum, o);

    float lse = m + logf(sum);
    if (p0) out[(size_t)node * FO + lane]      = v0 - lse;
    if (p1) out[(size_t)node * FO + lane + 32] = v1 - lse;
}

// ---------------- launch (R10 schedule: fork after prep) -------------------
extern "C" void kernel_launch(void* const* d_in, const int* in_sizes, int n_in,
                              void* d_out, int out_size) {
    const float* x  = (const float*)d_in[0];
    const int*   ei = (const int*)d_in[1];
    const float* w  = (const float*)d_in[2];
    const float* W1 = (const float*)d_in[3];
    const float* b1 = (const float*)d_in[4];
    const float* W2 = (const float*)d_in[5];
    const float* b2 = (const float*)d_in[6];
    float* out = (float*)d_out;

    cudaFuncSetAttribute(k_gemm1_mma,
                         cudaFuncAttributeMaxDynamicSharedMemorySize, GEMM1_SMEM);
    cudaFuncSetAttribute(k_gemm2_mma,
                         cudaFuncAttributeMaxDynamicSharedMemorySize, GEMM2_SMEM);

    k_prep<<<(FIN * FH + 255) / 256, 256>>>(W1, W2);

    // fork CSR-build branch
    cudaEventRecord(g_ss.ev_fork, 0);
    cudaStreamWaitEvent(g_ss.s2, g_ss.ev_fork, 0);

    // main stream: GEMM1 (depends only on prep)
    k_gemm1_mma<<<(NN + 127) / 128, 256, GEMM1_SMEM>>>(x);

    // side stream: CSR build
    k_deg_hist<<<(NE + 255) / 256, 256, 0, g_ss.s2>>>(ei, w);
    k_scan1   <<<NB_SCAN, 256, 0, g_ss.s2>>>();
    k_scan2   <<<1, 256, 0, g_ss.s2>>>();
    k_scan3   <<<NB_SCAN, 256, 0, g_ss.s2>>>();
    k_fill    <<<(NE + 255) / 256, 256, 0, g_ss.s2>>>(ei, w);

    // join
    cudaEventRecord(g_ss.ev_join, g_ss.s2);
    cudaStreamWaitEvent(0, g_ss.ev_join, 0);

    k_gather1        <<<(NN * 32 + 255) / 256, 256>>>(b1);
    k_gemm2_mma      <<<(NN + 127) / 128, 128, GEMM2_SMEM>>>();
    k_gather2_softmax<<<(NN * 32 + 255) / 256, 256>>>(b2, out);
}

// round 15
// speedup vs baseline: 1.3631x; 1.3631x over previous
#include <cuda_runtime.h>
#include <cuda_bf16.h>
#include <math_constants.h>
#include <cstdint>

#define NN 50000
#define NE 800000
#define FIN 512
#define FH 128
#define FO 40

#define NB_SCAN ((NN + 255) / 256)   // 196

// ---------------- scratch (device globals: no allocation allowed) ----------
__device__ float g_dinv[NN];
__device__ int   g_cnt[NN];
__device__ int   g_ptr[NN];
__device__ int   g_cur[NN];
__device__ int   g_bsum[256];
__device__ uint2 g_edges[NE];              // packed (src, norm) sorted by dst
__device__ float g_h1[NN * FH];
__device__ float g_h2[NN * FO];
__device__ __nv_bfloat16 g_r1h[NN * FH];   // relu(a1+b1) hi
__device__ __nv_bfloat16 g_r1l[NN * FH];   // relu(a1+b1) lo
__device__ __nv_bfloat16 g_W1t_hi[FH * FIN];   // W1^T hi, [n][k]
__device__ __nv_bfloat16 g_W1t_lo[FH * FIN];   // W1^T lo
__device__ __nv_bfloat16 g_W2t_hi[FO * FH];    // W2^T hi, [n][k]
__device__ __nv_bfloat16 g_W2t_lo[FO * FH];    // W2^T lo

// ---- side stream + events, created once at program init -------------------
struct SideStream {
    cudaStream_t s2;
    cudaEvent_t ev_fork, ev_join;
    SideStream() {
        cudaStreamCreateWithFlags(&s2, cudaStreamNonBlocking);
        cudaEventCreateWithFlags(&ev_fork, cudaEventDisableTiming);
        cudaEventCreateWithFlags(&ev_join, cudaEventDisableTiming);
    }
};
static SideStream g_ss;

// ================= warp-MMA helpers (arch-neutral PTX, sm_80+) =============
__device__ __forceinline__ uint32_t smem_to_u32(const void* p) {
    uint32_t a;
    asm("{ .reg .u64 t; cvta.to.shared.u64 t, %1; cvt.u32.u64 %0, t; }"
        : "=r"(a) : "l"(p));
    return a;
}

__device__ __forceinline__ void ldsm_x4(uint32_t* r, uint32_t addr) {
    asm volatile("ldmatrix.sync.aligned.m8n8.x4.shared.b16 {%0,%1,%2,%3}, [%4];"
        : "=r"(r[0]), "=r"(r[1]), "=r"(r[2]), "=r"(r[3]) : "r"(addr));
}

__device__ __forceinline__ void ldsm_x2(uint32_t* r, uint32_t addr) {
    asm volatile("ldmatrix.sync.aligned.m8n8.x2.shared.b16 {%0,%1}, [%2];"
        : "=r"(r[0]), "=r"(r[1]) : "r"(addr));
}

__device__ __forceinline__ void mma16816(float* d, const uint32_t* a,
                                         const uint32_t* b) {
    asm volatile("mma.sync.aligned.m16n8k16.row.col.f32.bf16.bf16.f32 "
        "{%0,%1,%2,%3}, {%4,%5,%6,%7}, {%8,%9}, {%0,%1,%2,%3};"
        : "+f"(d[0]), "+f"(d[1]), "+f"(d[2]), "+f"(d[3])
        : "r"(a[0]), "r"(a[1]), "r"(a[2]), "r"(a[3]), "r"(b[0]), "r"(b[1]));
}

#define CP_ASYNC16(dst, src) \
    asm volatile("cp.async.cg.shared.global [%0], [%1], 16;" \
        :: "r"(dst), "l"(src) : "memory")
#define CP_COMMIT() asm volatile("cp.async.commit_group;" ::: "memory")

#define SWZ(off) ((off) ^ (((off) >> 3) & 0x70))

// ---------------- fused init: dinv/cnt reset + W1 & W2 splits --------------
__global__ void k_prep(const float* __restrict__ W1,
                       const float* __restrict__ W2) {
    int i = blockIdx.x * blockDim.x + threadIdx.x;
    if (i < NN) { g_dinv[i] = 1.0f; g_cnt[i] = 0; }
    if (i < FIN * FH) {
        int k = i >> 7, n = i & 127;
        float v = W1[i];
        __nv_bfloat16 h = __float2bfloat16(v);
        g_W1t_hi[n * FIN + k] = h;
        g_W1t_lo[n * FIN + k] = __float2bfloat16(v - __bfloat162float(h));
    }
    if (i < FH * FO) {
        int k = i / FO, n = i % FO;
        float v = W2[i];
        __nv_bfloat16 h = __float2bfloat16(v);
        g_W2t_hi[n * FH + k] = h;
        g_W2t_lo[n * FH + k] = __float2bfloat16(v - __bfloat162float(h));
    }
}

__global__ void k_deg_hist(const int* __restrict__ ei, const float* __restrict__ w) {
    int e = blockIdx.x * blockDim.x + threadIdx.x;
    if (e < NE) {
        int c = ei[NE + e];
        atomicAdd(&g_dinv[c], w[e]);
        atomicAdd(&g_cnt[c], 1);
    }
}

// ---------------- 3-kernel exclusive scan (scan1 fuses dinv finalize) ------
__global__ void k_scan1() {
    __shared__ int sh[256];
    int tid = threadIdx.x;
    int i = blockIdx.x * 256 + tid;
    int v = (i < NN) ? g_cnt[i] : 0;
    if (i < NN) g_dinv[i] = rsqrtf(g_dinv[i]);   // deg >= 1 always
    sh[tid] = v;
    __syncthreads();
    #pragma unroll
    for (int o = 1; o < 256; o <<= 1) {
        int t = (tid >= o) ? sh[tid - o] : 0;
        __syncthreads();
        sh[tid] += t;
        __syncthreads();
    }
    if (i < NN) g_ptr[i] = sh[tid] - v;
    if (tid == 255) g_bsum[blockIdx.x] = sh[255];
}

__global__ void k_scan2() {
    __shared__ int sh[256];
    int tid = threadIdx.x;
    int v = (tid < NB_SCAN) ? g_bsum[tid] : 0;
    sh[tid] = v;
    __syncthreads();
    #pragma unroll
    for (int o = 1; o < 256; o <<= 1) {
        int t = (tid >= o) ? sh[tid - o] : 0;
        __syncthreads();
        sh[tid] += t;
        __syncthreads();
    }
    if (tid < NB_SCAN) g_bsum[tid] = sh[tid] - v;
}

__global__ void k_scan3() {
    int i = blockIdx.x * blockDim.x + threadIdx.x;
    if (i < NN) {
        int p = g_ptr[i] + g_bsum[i >> 8];
        g_ptr[i] = p;
        g_cur[i] = p;
    }
}

__global__ void k_fill(const int* __restrict__ ei, const float* __restrict__ w) {
    int e = blockIdx.x * blockDim.x + threadIdx.x;
    if (e < NE) {
        int r = ei[e];
        int c = ei[NE + e];
        float nrm = g_dinv[r] * w[e] * g_dinv[c];
        int pos = atomicAdd(&g_cur[c], 1);
        g_edges[pos] = make_uint2((unsigned)r, __float_as_uint(nrm));
    }
}

// ---------------- GEMM1 (mma.sync 3xBF16, pipelined): h1 = x @ W1 ----------
#define OFF_AH 0
#define OFF_AL 16384
#define OFF_B  32768
#define GEMM1_SMEM 98304

__global__ void __launch_bounds__(256) k_gemm1_mma(const float* __restrict__ A) {
    extern __shared__ char smem[];
    uint32_t sb = smem_to_u32(smem);
    int tid = threadIdx.x;
    int wid = tid >> 5;
    int lane = tid & 31;
    int row0 = blockIdx.x * 128;
    int warp_m = (wid & 3) * 32;
    int warp_n = (wid >> 2) * 64;

    float acc[2][8][4] = {};
    float4 areg[8];

    {
        uint32_t bb = sb + OFF_B;
        #pragma unroll
        for (int i = 0; i < 4; i++) {
            int slot = tid + i * 256;
            int r  = slot >> 3;
            int c8 = slot & 7;
            size_t src = (size_t)r * FIN + c8 * 8;
            uint32_t off = SWZ((uint32_t)(r * 128 + c8 * 16));
            CP_ASYNC16(bb + off,          (const void*)&g_W1t_hi[src]);
            CP_ASYNC16(bb + 16384 + off,  (const void*)&g_W1t_lo[src]);
        }
        CP_COMMIT();
        #pragma unroll
        for (int i = 0; i < 8; i++) {
            int slot = tid + i * 256;
            int r  = slot >> 4;
            int c4 = slot & 15;
            int gr = row0 + r;
            areg[i] = make_float4(0.f, 0.f, 0.f, 0.f);
            if (gr < NN) areg[i] = *(const float4*)&A[(size_t)gr * FIN + c4 * 4];
        }
    }

    for (int c = 0; c < 8; c++) {
        #pragma unroll
        for (int i = 0; i < 8; i++) {
            int slot = tid + i * 256;
            int r  = slot >> 4;
            int c4 = slot & 15;
            float4 v = areg[i];
            __nv_bfloat162 h01 = __floats2bfloat162_rn(v.x, v.y);
            __nv_bfloat162 h23 = __floats2bfloat162_rn(v.z, v.w);
            float2 hf01 = __bfloat1622float2(h01);
            float2 hf23 = __bfloat1622float2(h23);
            __nv_bfloat162 l01 = __floats2bfloat162_rn(v.x - hf01.x, v.y - hf01.y);
            __nv_bfloat162 l23 = __floats2bfloat162_rn(v.z - hf23.x, v.w - hf23.y);
            uint32_t off = SWZ((uint32_t)(r * 128 + c4 * 8));
            *(uint2*)(smem + OFF_AH + off) =
                make_uint2(*(uint32_t*)&h01, *(uint32_t*)&h23);
            *(uint2*)(smem + OFF_AL + off) =
                make_uint2(*(uint32_t*)&l01, *(uint32_t*)&l23);
        }

        if (c < 7) {
            int k1 = (c + 1) * 64;
            uint32_t bb = sb + OFF_B + ((c + 1) & 1) * 32768;
            #pragma unroll
            for (int i = 0; i < 4; i++) {
                int slot = tid + i * 256;
                int r  = slot >> 3;
                int c8 = slot & 7;
                size_t src = (size_t)r * FIN + k1 + c8 * 8;
                uint32_t off = SWZ((uint32_t)(r * 128 + c8 * 16));
                CP_ASYNC16(bb + off,         (const void*)&g_W1t_hi[src]);
                CP_ASYNC16(bb + 16384 + off, (const void*)&g_W1t_lo[src]);
            }
            CP_COMMIT();
            #pragma unroll
            for (int i = 0; i < 8; i++) {
                int slot = tid + i * 256;
                int r  = slot >> 4;
                int c4 = slot & 15;
                int gr = row0 + r;
                areg[i] = make_float4(0.f, 0.f, 0.f, 0.f);
                if (gr < NN)
                    areg[i] = *(const float4*)&A[(size_t)gr * FIN + k1 + c4 * 4];
            }
            asm volatile("cp.async.wait_group 1;" ::: "memory");
        } else {
            asm volatile("cp.async.wait_group 0;" ::: "memory");
        }
        __syncthreads();

        uint32_t offBH = (uint32_t)OFF_B + (c & 1) * 32768u;
        uint32_t offBL = offBH + 16384u;
        #pragma unroll
        for (int pass = 0; pass < 3; pass++) {
            uint32_t offA = (pass == 2) ? (uint32_t)OFF_AL : (uint32_t)OFF_AH;
            uint32_t offB = (pass == 1) ? offBL : offBH;
            #pragma unroll
            for (int ks = 0; ks < 4; ks++) {
                int t = lane >> 3;
                uint32_t afrag[2][4];
                #pragma unroll
                for (int mt = 0; mt < 2; mt++) {
                    int r  = warp_m + mt * 16 + ((t & 1) << 3) + (lane & 7);
                    int kk = ks * 16 + ((t >> 1) << 3);
                    ldsm_x4(afrag[mt], sb + offA + SWZ((uint32_t)(r * 128 + kk * 2)));
                }
                uint32_t bfrag[8][2];
                #pragma unroll
                for (int nt2 = 0; nt2 < 4; nt2++) {
                    int n  = warp_n + nt2 * 16 + ((t >> 1) << 3) + (lane & 7);
                    int kk = ks * 16 + ((t & 1) << 3);
                    uint32_t tmp[4];
                    ldsm_x4(tmp, sb + offB + SWZ((uint32_t)(n * 128 + kk * 2)));
                    bfrag[nt2 * 2][0]     = tmp[0];
                    bfrag[nt2 * 2][1]     = tmp[1];
                    bfrag[nt2 * 2 + 1][0] = tmp[2];
                    bfrag[nt2 * 2 + 1][1] = tmp[3];
                }
                #pragma unroll
                for (int mt = 0; mt < 2; mt++)
                    #pragma unroll
                    for (int nt = 0; nt < 8; nt++)
                        mma16816(acc[mt][nt], afrag[mt], bfrag[nt]);
            }
        }
        __syncthreads();
    }

    #pragma unroll
    for (int mt = 0; mt < 2; mt++) {
        int m0 = row0 + warp_m + mt * 16 + (lane >> 2);
        #pragma unroll
        for (int nt = 0; nt < 8; nt++) {
            int n = warp_n + nt * 8 + (lane & 3) * 2;
            if (m0 < NN)
                *(float2*)&g_h1[(size_t)m0 * FH + n] =
                    make_float2(acc[mt][nt][0], acc[mt][nt][1]);
            if (m0 + 8 < NN)
                *(float2*)&g_h1[(size_t)(m0 + 8) * FH + n] =
                    make_float2(acc[mt][nt][2], acc[mt][nt][3]);
        }
    }
}

// ------- layer-1 gather + bias + relu + bf16 hi/lo split (fused) ----------
// warp-per-node: maximal memory-level parallelism for the irregular gather.
__global__ void __launch_bounds__(256) k_gather1(const float* __restrict__ b1) {
    int node = (blockIdx.x * blockDim.x + threadIdx.x) >> 5;
    int lane = threadIdx.x & 31;
    if (node >= NN) return;

    int start = g_ptr[node];
    int cnt   = g_cnt[node];
    float s = g_dinv[node];
    s *= s;

    float4 acc = *(const float4*)&g_h1[(size_t)node * FH + lane * 4];
    acc.x *= s; acc.y *= s; acc.z *= s; acc.w *= s;

    int i = 0;
    for (; i + 4 <= cnt; i += 4) {
        uint2 e0 = g_edges[start + i];
        uint2 e1 = g_edges[start + i + 1];
        uint2 e2 = g_edges[start + i + 2];
        uint2 e3 = g_edges[start + i + 3];
        float n0 = __uint_as_float(e0.y);
        float n1 = __uint_as_float(e1.y);
        float n2 = __uint_as_float(e2.y);
        float n3 = __uint_as_float(e3.y);
        float4 v0 = *(const float4*)&g_h1[(size_t)e0.x * FH + lane * 4];
        float4 v1 = *(const float4*)&g_h1[(size_t)e1.x * FH + lane * 4];
        float4 v2 = *(const float4*)&g_h1[(size_t)e2.x * FH + lane * 4];
        float4 v3 = *(const float4*)&g_h1[(size_t)e3.x * FH + lane * 4];
        acc.x += v0.x * n0 + v1.x * n1 + v2.x * n2 + v3.x * n3;
        acc.y += v0.y * n0 + v1.y * n1 + v2.y * n2 + v3.y * n3;
        acc.z += v0.z * n0 + v1.z * n1 + v2.z * n2 + v3.z * n3;
        acc.w += v0.w * n0 + v1.w * n1 + v2.w * n2 + v3.w * n3;
    }
    for (; i < cnt; i++) {
        uint2 e0 = g_edges[start + i];
        float n0 = __uint_as_float(e0.y);
        float4 v0 = *(const float4*)&g_h1[(size_t)e0.x * FH + lane * 4];
        acc.x += v0.x * n0;
        acc.y += v0.y * n0;
        acc.z += v0.z * n0;
        acc.w += v0.w * n0;
    }

    float4 bv = *(const float4*)&b1[lane * 4];
    acc.x = fmaxf(acc.x + bv.x, 0.f);
    acc.y = fmaxf(acc.y + bv.y, 0.f);
    acc.z = fmaxf(acc.z + bv.z, 0.f);
    acc.w = fmaxf(acc.w + bv.w, 0.f);
    __nv_bfloat162 h01 = __floats2bfloat162_rn(acc.x, acc.y);
    __nv_bfloat162 h23 = __floats2bfloat162_rn(acc.z, acc.w);
    float2 hf01 = __bfloat1622float2(h01);
    float2 hf23 = __bfloat1622float2(h23);
    __nv_bfloat162 l01 = __floats2bfloat162_rn(acc.x - hf01.x, acc.y - hf01.y);
    __nv_bfloat162 l23 = __floats2bfloat162_rn(acc.z - hf23.x, acc.w - hf23.y);
    size_t dst = (size_t)node * FH + lane * 4;
    *(uint2*)&g_r1h[dst] = make_uint2(*(uint32_t*)&h01, *(uint32_t*)&h23);
    *(uint2*)&g_r1l[dst] = make_uint2(*(uint32_t*)&l01, *(uint32_t*)&l23);
}

// ---------------- GEMM2 (mma.sync 3xBF16): h2 = r1 @ W2 --------------------
#define G2_AH 0
#define G2_AL 32768
#define G2_BH 65536
#define G2_BL 75776
#define GEMM2_SMEM 86016

__global__ void __launch_bounds__(128) k_gemm2_mma() {
    extern __shared__ char smem[];
    uint32_t sb = smem_to_u32(smem);
    int tid = threadIdx.x;
    int wid = tid >> 5;
    int lane = tid & 31;
    int row0 = blockIdx.x * 128;

    #pragma unroll
    for (int i = 0; i < 16; i++) {
        int slot = tid + i * 128;
        int r   = slot >> 4;
        int c16 = slot & 15;
        int ch  = c16 >> 3;
        int c8  = c16 & 7;
        int gr  = row0 + r;
        uint4 vh = make_uint4(0u, 0u, 0u, 0u), vl = vh;
        if (gr < NN) {
            size_t src = (size_t)gr * FH + ch * 64 + c8 * 8;
            vh = *(const uint4*)&g_r1h[src];
            vl = *(const uint4*)&g_r1l[src];
        }
        uint32_t off = SWZ((uint32_t)(r * 128 + c8 * 16));
        *(uint4*)(smem + G2_AH + ch * 16384 + off) = vh;
        *(uint4*)(smem + G2_AL + ch * 16384 + off) = vl;
    }
    for (int slot = tid; slot < FO * 16; slot += 128) {
        int r   = slot >> 4;
        int c16 = slot & 15;
        int ch  = c16 >> 3;
        int c8  = c16 & 7;
        size_t src = (size_t)r * FH + ch * 64 + c8 * 8;
        uint4 vh = *(const uint4*)&g_W2t_hi[src];
        uint4 vl = *(const uint4*)&g_W2t_lo[src];
        uint32_t off = SWZ((uint32_t)(r * 128 + c8 * 16));
        *(uint4*)(smem + G2_BH + ch * 5120 + off) = vh;
        *(uint4*)(smem + G2_BL + ch * 5120 + off) = vl;
    }
    __syncthreads();

    float acc[2][5][4] = {};
    int warp_m = wid * 32;
    int t = lane >> 3;

    #pragma unroll
    for (int pass = 0; pass < 3; pass++) {
        uint32_t baseA = (pass == 2) ? (uint32_t)G2_AL : (uint32_t)G2_AH;
        uint32_t baseB = (pass == 1) ? (uint32_t)G2_BL : (uint32_t)G2_BH;
        #pragma unroll
        for (int ch = 0; ch < 2; ch++) {
            uint32_t offA = baseA + ch * 16384u;
            uint32_t offB = baseB + ch * 5120u;
            #pragma unroll
            for (int ks = 0; ks < 4; ks++) {
                uint32_t afrag[2][4];
                #pragma unroll
                for (int mt = 0; mt < 2; mt++) {
                    int r  = warp_m + mt * 16 + ((t & 1) << 3) + (lane & 7);
                    int kk = ks * 16 + ((t >> 1) << 3);
                    ldsm_x4(afrag[mt], sb + offA + SWZ((uint32_t)(r * 128 + kk * 2)));
                }
                uint32_t bfrag[5][2];
                #pragma unroll
                for (int g = 0; g < 2; g++) {
                    int n  = g * 16 + ((t >> 1) << 3) + (lane & 7);
                    int kk = ks * 16 + ((t & 1) << 3);
                    uint32_t tmp[4];
                    ldsm_x4(tmp, sb + offB + SWZ((uint32_t)(n * 128 + kk * 2)));
                    bfrag[g * 2][0]     = tmp[0];
                    bfrag[g * 2][1]     = tmp[1];
                    bfrag[g * 2 + 1][0] = tmp[2];
                    bfrag[g * 2 + 1][1] = tmp[3];
                }
                {
                    int l  = lane & 15;
                    int n  = 32 + (l & 7);
                    int kk = ks * 16 + ((l >> 3) << 3);
                    uint32_t tmp2[2];
                    ldsm_x2(tmp2, sb + offB + SWZ((uint32_t)(n * 128 + kk * 2)));
                    bfrag[4][0] = tmp2[0];
                    bfrag[4][1] = tmp2[1];
                }
                #pragma unroll
                for (int mt = 0; mt < 2; mt++)
                    #pragma unroll
                    for (int nt = 0; nt < 5; nt++)
                        mma16816(acc[mt][nt], afrag[mt], bfrag[nt]);
            }
        }
    }

    #pragma unroll
    for (int mt = 0; mt < 2; mt++) {
        int m0 = row0 + warp_m + mt * 16 + (lane >> 2);
        #pragma unroll
        for (int nt = 0; nt < 5; nt++) {
            int n = nt * 8 + (lane & 3) * 2;
            if (m0 < NN)
                *(float2*)&g_h2[(size_t)m0 * FO + n] =
                    make_float2(acc[mt][nt][0], acc[mt][nt][1]);
            if (m0 + 8 < NN)
                *(float2*)&g_h2[(size_t)(m0 + 8) * FO + n] =
                    make_float2(acc[mt][nt][2], acc[mt][nt][3]);
        }
    }
}

// ---------------- layer-2 gather + b2 + log_softmax ----------------
__global__ void __launch_bounds__(256) k_gather2_softmax(
        const float* __restrict__ b2, float* __restrict__ out) {
    int node = (blockIdx.x * blockDim.x + threadIdx.x) >> 5;
    int lane = threadIdx.x & 31;
    if (node >= NN) return;

    int start = g_ptr[node];
    int cnt   = g_cnt[node];
    float s = g_dinv[node];
    s *= s;

    bool p0 = (lane < FO);
    bool p1 = (lane + 32 < FO);

    const float* self = &g_h2[(size_t)node * FO];
    float acc0 = p0 ? self[lane] * s : 0.f;
    float acc1 = p1 ? self[lane + 32] * s : 0.f;

    int i = 0;
    for (; i + 2 <= cnt; i += 2) {
        uint2 e0 = g_edges[start + i];
        uint2 e1 = g_edges[start + i + 1];
        float n0 = __uint_as_float(e0.y);
        float n1 = __uint_as_float(e1.y);
        const float* h0 = &g_h2[(size_t)e0.x * FO];
        const float* h1p = &g_h2[(size_t)e1.x * FO];
        if (p0) acc0 += h0[lane] * n0 + h1p[lane] * n1;
        if (p1) acc1 += h0[lane + 32] * n0 + h1p[lane + 32] * n1;
    }
    if (i < cnt) {
        uint2 e = g_edges[start + i];
        float nrm = __uint_as_float(e.y);
        const float* hr = &g_h2[(size_t)e.x * FO];
        if (p0) acc0 += hr[lane] * nrm;
        if (p1) acc1 += hr[lane + 32] * nrm;
    }

    float v0 = p0 ? acc0 + b2[lane] : -CUDART_INF_F;
    float v1 = p1 ? acc1 + b2[lane + 32] : -CUDART_INF_F;

    float m = fmaxf(v0, v1);
    #pragma unroll
    for (int o = 16; o; o >>= 1) m = fmaxf(m, __shfl_xor_sync(0xffffffffu, m, o));

    float sum = (p0 ? expf(v0 - m) : 0.f) + (p1 ? expf(v1 - m) : 0.f);
    #pragma unroll
    for (int o = 16; o; o >>= 1) sum += __shfl_xor_sync(0xffffffffu, sum, o);

    float lse = m + logf(sum);
    if (p0) out[(size_t)node * FO + lane]      = v0 - lse;
    if (p1) out[(size_t)node * FO + lane + 32] = v1 - lse;
}

// ---------------- launch ----------------
// Fork: GEMM1 runs on the main (capture) stream concurrently with the CSR
// build branch on g_ss.s2. Standard capture fork/join via events.
extern "C" void kernel_launch(void* const* d_in, const int* in_sizes, int n_in,
                              void* d_out, int out_size) {
    const float* x  = (const float*)d_in[0];
    const int*   ei = (const int*)d_in[1];
    const float* w  = (const float*)d_in[2];
    const float* W1 = (const float*)d_in[3];
    const float* b1 = (const float*)d_in[4];
    const float* W2 = (const float*)d_in[5];
    const float* b2 = (const float*)d_in[6];
    float* out = (float*)d_out;

    cudaFuncSetAttribute(k_gemm1_mma,
                         cudaFuncAttributeMaxDynamicSharedMemorySize, GEMM1_SMEM);
    cudaFuncSetAttribute(k_gemm2_mma,
                         cudaFuncAttributeMaxDynamicSharedMemorySize, GEMM2_SMEM);

    k_prep<<<(FIN * FH + 255) / 256, 256>>>(W1, W2);

    // fork CSR-build branch
    cudaEventRecord(g_ss.ev_fork, 0);
    cudaStreamWaitEvent(g_ss.s2, g_ss.ev_fork, 0);

    // main stream: GEMM1 (depends only on prep)
    k_gemm1_mma<<<(NN + 127) / 128, 256, GEMM1_SMEM>>>(x);

    // side stream: CSR build
    k_deg_hist<<<(NE + 255) / 256, 256, 0, g_ss.s2>>>(ei, w);
    k_scan1   <<<NB_SCAN, 256, 0, g_ss.s2>>>();
    k_scan2   <<<1, 256, 0, g_ss.s2>>>();
    k_scan3   <<<NB_SCAN, 256, 0, g_ss.s2>>>();
    k_fill    <<<(NE + 255) / 256, 256, 0, g_ss.s2>>>(ei, w);

    // join
    cudaEventRecord(g_ss.ev_join, g_ss.s2);
    cudaStreamWaitEvent(0, g_ss.ev_join, 0);

    k_gather1        <<<(NN * 32 + 255) / 256, 256>>>(b1);
    k_gemm2_mma      <<<(NN + 127) / 128, 128, GEMM2_SMEM>>>();
    k_gather2_softmax<<<(NN * 32 + 255) / 256, 256>>>(b2, out);
}

// round 16
// speedup vs baseline: 1.4165x; 1.0392x over previous
#include <cuda_runtime.h>
#include <cuda_bf16.h>
#include <math_constants.h>
#include <cstdint>

#define NN 50000
#define NE 800000
#define FIN 512
#define FH 128
#define FO 40

#define NB_SCAN ((NN + 255) / 256)   // 196

// ---------------- scratch (device globals: no allocation allowed) ----------
__device__ float g_dinv[NN];
__device__ int   g_cnt[NN];
__device__ int   g_ptr[NN];
__device__ int   g_cur[NN];
__device__ int   g_bsum[256];
__device__ uint2 g_edges[NE];              // packed (src, norm) sorted by dst
__device__ float g_h1[NN * FH];
__device__ float g_h2[NN * FO];
__device__ __nv_bfloat16 g_r1h[NN * FH];   // relu(a1+b1) hi
__device__ __nv_bfloat16 g_r1l[NN * FH];   // relu(a1+b1) lo
__device__ __nv_bfloat16 g_W1t_hi[FH * FIN];   // W1^T hi, [n][k]
__device__ __nv_bfloat16 g_W1t_lo[FH * FIN];   // W1^T lo
__device__ __nv_bfloat16 g_W2t_hi[FO * FH];    // W2^T hi, [n][k]
__device__ __nv_bfloat16 g_W2t_lo[FO * FH];    // W2^T lo

// ---- side stream + events, created once at program init -------------------
struct SideStream {
    cudaStream_t s2;
    cudaEvent_t ev_fork, ev_join;
    SideStream() {
        cudaStreamCreateWithFlags(&s2, cudaStreamNonBlocking);
        cudaEventCreateWithFlags(&ev_fork, cudaEventDisableTiming);
        cudaEventCreateWithFlags(&ev_join, cudaEventDisableTiming);
    }
};
static SideStream g_ss;

// ================= warp-MMA helpers (arch-neutral PTX, sm_80+) =============
__device__ __forceinline__ uint32_t smem_to_u32(const void* p) {
    uint32_t a;
    asm("{ .reg .u64 t; cvta.to.shared.u64 t, %1; cvt.u32.u64 %0, t; }"
        : "=r"(a) : "l"(p));
    return a;
}

__device__ __forceinline__ void ldsm_x4(uint32_t* r, uint32_t addr) {
    asm volatile("ldmatrix.sync.aligned.m8n8.x4.shared.b16 {%0,%1,%2,%3}, [%4];"
        : "=r"(r[0]), "=r"(r[1]), "=r"(r[2]), "=r"(r[3]) : "r"(addr));
}

__device__ __forceinline__ void ldsm_x2(uint32_t* r, uint32_t addr) {
    asm volatile("ldmatrix.sync.aligned.m8n8.x2.shared.b16 {%0,%1}, [%2];"
        : "=r"(r[0]), "=r"(r[1]) : "r"(addr));
}

__device__ __forceinline__ void mma16816(float* d, const uint32_t* a,
                                         const uint32_t* b) {
    asm volatile("mma.sync.aligned.m16n8k16.row.col.f32.bf16.bf16.f32 "
        "{%0,%1,%2,%3}, {%4,%5,%6,%7}, {%8,%9}, {%0,%1,%2,%3};"
        : "+f"(d[0]), "+f"(d[1]), "+f"(d[2]), "+f"(d[3])
        : "r"(a[0]), "r"(a[1]), "r"(a[2]), "r"(a[3]), "r"(b[0]), "r"(b[1]));
}

#define CP_ASYNC16(dst, src) \
    asm volatile("cp.async.cg.shared.global [%0], [%1], 16;" \
        :: "r"(dst), "l"(src) : "memory")
#define CP_COMMIT() asm volatile("cp.async.commit_group;" ::: "memory")

#define SWZ(off) ((off) ^ (((off) >> 3) & 0x70))

// ---------------- fused init: dinv/cnt reset + W1 & W2 splits --------------
__global__ void k_prep(const float* __restrict__ W1,
                       const float* __restrict__ W2) {
    int i = blockIdx.x * blockDim.x + threadIdx.x;
    if (i < NN) { g_dinv[i] = 1.0f; g_cnt[i] = 0; }
    if (i < FIN * FH) {
        int k = i >> 7, n = i & 127;
        float v = W1[i];
        __nv_bfloat16 h = __float2bfloat16(v);
        g_W1t_hi[n * FIN + k] = h;
        g_W1t_lo[n * FIN + k] = __float2bfloat16(v - __bfloat162float(h));
    }
    if (i < FH * FO) {
        int k = i / FO, n = i % FO;
        float v = W2[i];
        __nv_bfloat16 h = __float2bfloat16(v);
        g_W2t_hi[n * FH + k] = h;
        g_W2t_lo[n * FH + k] = __float2bfloat16(v - __bfloat162float(h));
    }
}

__global__ void k_deg_hist(const int* __restrict__ ei, const float* __restrict__ w) {
    int e = blockIdx.x * blockDim.x + threadIdx.x;
    if (e < NE) {
        int c = ei[NE + e];
        atomicAdd(&g_dinv[c], w[e]);
        atomicAdd(&g_cnt[c], 1);
    }
}

// ---------------- 3-kernel exclusive scan (scan1 fuses dinv finalize) ------
__global__ void k_scan1() {
    __shared__ int sh[256];
    int tid = threadIdx.x;
    int i = blockIdx.x * 256 + tid;
    int v = (i < NN) ? g_cnt[i] : 0;
    if (i < NN) g_dinv[i] = rsqrtf(g_dinv[i]);   // deg >= 1 always
    sh[tid] = v;
    __syncthreads();
    #pragma unroll
    for (int o = 1; o < 256; o <<= 1) {
        int t = (tid >= o) ? sh[tid - o] : 0;
        __syncthreads();
        sh[tid] += t;
        __syncthreads();
    }
    if (i < NN) g_ptr[i] = sh[tid] - v;
    if (tid == 255) g_bsum[blockIdx.x] = sh[255];
}

__global__ void k_scan2() {
    __shared__ int sh[256];
    int tid = threadIdx.x;
    int v = (tid < NB_SCAN) ? g_bsum[tid] : 0;
    sh[tid] = v;
    __syncthreads();
    #pragma unroll
    for (int o = 1; o < 256; o <<= 1) {
        int t = (tid >= o) ? sh[tid - o] : 0;
        __syncthreads();
        sh[tid] += t;
        __syncthreads();
    }
    if (tid < NB_SCAN) g_bsum[tid] = sh[tid] - v;
}

__global__ void k_scan3() {
    int i = blockIdx.x * blockDim.x + threadIdx.x;
    if (i < NN) {
        int p = g_ptr[i] + g_bsum[i >> 8];
        g_ptr[i] = p;
        g_cur[i] = p;
    }
}

__global__ void k_fill(const int* __restrict__ ei, const float* __restrict__ w) {
    int e = blockIdx.x * blockDim.x + threadIdx.x;
    if (e < NE) {
        int r = ei[e];
        int c = ei[NE + e];
        float nrm = g_dinv[r] * w[e] * g_dinv[c];
        int pos = atomicAdd(&g_cur[c], 1);
        g_edges[pos] = make_uint2((unsigned)r, __float_as_uint(nrm));
    }
}

// ---------------- GEMM1 (mma.sync 3xBF16, pipelined): h1 = x @ W1 ----------
// Fragment-reuse inner loop: per k-step, load A_hi/A_lo/B_hi/B_lo fragments
// ONCE and issue all three products (hi*hi, hi*lo, lo*hi). LDSM count drops
// 72 -> 48 per chunk per warp vs the per-pass loader.
#define OFF_AH 0
#define OFF_AL 16384
#define OFF_B  32768
#define GEMM1_SMEM 98304

__global__ void __launch_bounds__(256) k_gemm1_mma(const float* __restrict__ A) {
    extern __shared__ char smem[];
    uint32_t sb = smem_to_u32(smem);
    int tid = threadIdx.x;
    int wid = tid >> 5;
    int lane = tid & 31;
    int row0 = blockIdx.x * 128;
    int warp_m = (wid & 3) * 32;
    int warp_n = (wid >> 2) * 64;

    float acc[2][8][4] = {};
    float4 areg[8];

    {
        uint32_t bb = sb + OFF_B;
        #pragma unroll
        for (int i = 0; i < 4; i++) {
            int slot = tid + i * 256;
            int r  = slot >> 3;
            int c8 = slot & 7;
            size_t src = (size_t)r * FIN + c8 * 8;
            uint32_t off = SWZ((uint32_t)(r * 128 + c8 * 16));
            CP_ASYNC16(bb + off,          (const void*)&g_W1t_hi[src]);
            CP_ASYNC16(bb + 16384 + off,  (const void*)&g_W1t_lo[src]);
        }
        CP_COMMIT();
        #pragma unroll
        for (int i = 0; i < 8; i++) {
            int slot = tid + i * 256;
            int r  = slot >> 4;
            int c4 = slot & 15;
            int gr = row0 + r;
            areg[i] = make_float4(0.f, 0.f, 0.f, 0.f);
            if (gr < NN) areg[i] = *(const float4*)&A[(size_t)gr * FIN + c4 * 4];
        }
    }

    for (int c = 0; c < 8; c++) {
        #pragma unroll
        for (int i = 0; i < 8; i++) {
            int slot = tid + i * 256;
            int r  = slot >> 4;
            int c4 = slot & 15;
            float4 v = areg[i];
            __nv_bfloat162 h01 = __floats2bfloat162_rn(v.x, v.y);
            __nv_bfloat162 h23 = __floats2bfloat162_rn(v.z, v.w);
            float2 hf01 = __bfloat1622float2(h01);
            float2 hf23 = __bfloat1622float2(h23);
            __nv_bfloat162 l01 = __floats2bfloat162_rn(v.x - hf01.x, v.y - hf01.y);
            __nv_bfloat162 l23 = __floats2bfloat162_rn(v.z - hf23.x, v.w - hf23.y);
            uint32_t off = SWZ((uint32_t)(r * 128 + c4 * 8));
            *(uint2*)(smem + OFF_AH + off) =
                make_uint2(*(uint32_t*)&h01, *(uint32_t*)&h23);
            *(uint2*)(smem + OFF_AL + off) =
                make_uint2(*(uint32_t*)&l01, *(uint32_t*)&l23);
        }

        if (c < 7) {
            int k1 = (c + 1) * 64;
            uint32_t bb = sb + OFF_B + ((c + 1) & 1) * 32768;
            #pragma unroll
            for (int i = 0; i < 4; i++) {
                int slot = tid + i * 256;
                int r  = slot >> 3;
                int c8 = slot & 7;
                size_t src = (size_t)r * FIN + k1 + c8 * 8;
                uint32_t off = SWZ((uint32_t)(r * 128 + c8 * 16));
                CP_ASYNC16(bb + off,         (const void*)&g_W1t_hi[src]);
                CP_ASYNC16(bb + 16384 + off, (const void*)&g_W1t_lo[src]);
            }
            CP_COMMIT();
            #pragma unroll
            for (int i = 0; i < 8; i++) {
                int slot = tid + i * 256;
                int r  = slot >> 4;
                int c4 = slot & 15;
                int gr = row0 + r;
                areg[i] = make_float4(0.f, 0.f, 0.f, 0.f);
                if (gr < NN)
                    areg[i] = *(const float4*)&A[(size_t)gr * FIN + k1 + c4 * 4];
            }
            asm volatile("cp.async.wait_group 1;" ::: "memory");
        } else {
            asm volatile("cp.async.wait_group 0;" ::: "memory");
        }
        __syncthreads();

        uint32_t offBH = (uint32_t)OFF_B + (c & 1) * 32768u;
        uint32_t offBL = offBH + 16384u;
        #pragma unroll
        for (int ks = 0; ks < 4; ks++) {
            int t = lane >> 3;
            int ar = ((t & 1) << 3) + (lane & 7);
            int ak = ks * 16 + ((t >> 1) << 3);
            int bn = ((t >> 1) << 3) + (lane & 7);
            int bk = ks * 16 + ((t & 1) << 3);

            // A fragments (hi and lo), loaded once
            uint32_t afH[2][4], afL[2][4];
            #pragma unroll
            for (int mt = 0; mt < 2; mt++) {
                uint32_t o = SWZ((uint32_t)((warp_m + mt * 16 + ar) * 128 + ak * 2));
                ldsm_x4(afH[mt], sb + OFF_AH + o);
                ldsm_x4(afL[mt], sb + OFF_AL + o);
            }
            // B fragments (hi and lo), loaded once
            uint32_t bfH[8][2], bfL[8][2];
            #pragma unroll
            for (int nt2 = 0; nt2 < 4; nt2++) {
                uint32_t o = SWZ((uint32_t)((warp_n + nt2 * 16 + bn) * 128 + bk * 2));
                uint32_t tmp[4];
                ldsm_x4(tmp, sb + offBH + o);
                bfH[nt2 * 2][0]     = tmp[0];
                bfH[nt2 * 2][1]     = tmp[1];
                bfH[nt2 * 2 + 1][0] = tmp[2];
                bfH[nt2 * 2 + 1][1] = tmp[3];
                ldsm_x4(tmp, sb + offBL + o);
                bfL[nt2 * 2][0]     = tmp[0];
                bfL[nt2 * 2][1]     = tmp[1];
                bfL[nt2 * 2 + 1][0] = tmp[2];
                bfL[nt2 * 2 + 1][1] = tmp[3];
            }

            // three products: hi*hi + hi*lo + lo*hi
            #pragma unroll
            for (int mt = 0; mt < 2; mt++)
                #pragma unroll
                for (int nt = 0; nt < 8; nt++)
                    mma16816(acc[mt][nt], afH[mt], bfH[nt]);
            #pragma unroll
            for (int mt = 0; mt < 2; mt++)
                #pragma unroll
                for (int nt = 0; nt < 8; nt++)
                    mma16816(acc[mt][nt], afH[mt], bfL[nt]);
            #pragma unroll
            for (int mt = 0; mt < 2; mt++)
                #pragma unroll
                for (int nt = 0; nt < 8; nt++)
                    mma16816(acc[mt][nt], afL[mt], bfH[nt]);
        }
        __syncthreads();
    }

    #pragma unroll
    for (int mt = 0; mt < 2; mt++) {
        int m0 = row0 + warp_m + mt * 16 + (lane >> 2);
        #pragma unroll
        for (int nt = 0; nt < 8; nt++) {
            int n = warp_n + nt * 8 + (lane & 3) * 2;
            if (m0 < NN)
                *(float2*)&g_h1[(size_t)m0 * FH + n] =
                    make_float2(acc[mt][nt][0], acc[mt][nt][1]);
            if (m0 + 8 < NN)
                *(float2*)&g_h1[(size_t)(m0 + 8) * FH + n] =
                    make_float2(acc[mt][nt][2], acc[mt][nt][3]);
        }
    }
}

// ------- layer-1 gather + bias + relu + bf16 hi/lo split (fused) ----------
// warp-per-node: maximal memory-level parallelism for the irregular gather.
__global__ void __launch_bounds__(256) k_gather1(const float* __restrict__ b1) {
    int node = (blockIdx.x * blockDim.x + threadIdx.x) >> 5;
    int lane = threadIdx.x & 31;
    if (node >= NN) return;

    int start = g_ptr[node];
    int cnt   = g_cnt[node];
    float s = g_dinv[node];
    s *= s;

    float4 acc = *(const float4*)&g_h1[(size_t)node * FH + lane * 4];
    acc.x *= s; acc.y *= s; acc.z *= s; acc.w *= s;

    int i = 0;
    for (; i + 4 <= cnt; i += 4) {
        uint2 e0 = g_edges[start + i];
        uint2 e1 = g_edges[start + i + 1];
        uint2 e2 = g_edges[start + i + 2];
        uint2 e3 = g_edges[start + i + 3];
        float n0 = __uint_as_float(e0.y);
        float n1 = __uint_as_float(e1.y);
        float n2 = __uint_as_float(e2.y);
        float n3 = __uint_as_float(e3.y);
        float4 v0 = *(const float4*)&g_h1[(size_t)e0.x * FH + lane * 4];
        float4 v1 = *(const float4*)&g_h1[(size_t)e1.x * FH + lane * 4];
        float4 v2 = *(const float4*)&g_h1[(size_t)e2.x * FH + lane * 4];
        float4 v3 = *(const float4*)&g_h1[(size_t)e3.x * FH + lane * 4];
        acc.x += v0.x * n0 + v1.x * n1 + v2.x * n2 + v3.x * n3;
        acc.y += v0.y * n0 + v1.y * n1 + v2.y * n2 + v3.y * n3;
        acc.z += v0.z * n0 + v1.z * n1 + v2.z * n2 + v3.z * n3;
        acc.w += v0.w * n0 + v1.w * n1 + v2.w * n2 + v3.w * n3;
    }
    for (; i < cnt; i++) {
        uint2 e0 = g_edges[start + i];
        float n0 = __uint_as_float(e0.y);
        float4 v0 = *(const float4*)&g_h1[(size_t)e0.x * FH + lane * 4];
        acc.x += v0.x * n0;
        acc.y += v0.y * n0;
        acc.z += v0.z * n0;
        acc.w += v0.w * n0;
    }

    float4 bv = *(const float4*)&b1[lane * 4];
    acc.x = fmaxf(acc.x + bv.x, 0.f);
    acc.y = fmaxf(acc.y + bv.y, 0.f);
    acc.z = fmaxf(acc.z + bv.z, 0.f);
    acc.w = fmaxf(acc.w + bv.w, 0.f);
    __nv_bfloat162 h01 = __floats2bfloat162_rn(acc.x, acc.y);
    __nv_bfloat162 h23 = __floats2bfloat162_rn(acc.z, acc.w);
    float2 hf01 = __bfloat1622float2(h01);
    float2 hf23 = __bfloat1622float2(h23);
    __nv_bfloat162 l01 = __floats2bfloat162_rn(acc.x - hf01.x, acc.y - hf01.y);
    __nv_bfloat162 l23 = __floats2bfloat162_rn(acc.z - hf23.x, acc.w - hf23.y);
    size_t dst = (size_t)node * FH + lane * 4;
    *(uint2*)&g_r1h[dst] = make_uint2(*(uint32_t*)&h01, *(uint32_t*)&h23);
    *(uint2*)&g_r1l[dst] = make_uint2(*(uint32_t*)&l01, *(uint32_t*)&l23);
}

// ---------------- GEMM2 (mma.sync 3xBF16): h2 = r1 @ W2 --------------------
#define G2_AH 0
#define G2_AL 32768
#define G2_BH 65536
#define G2_BL 75776
#define GEMM2_SMEM 86016

__global__ void __launch_bounds__(128) k_gemm2_mma() {
    extern __shared__ char smem[];
    uint32_t sb = smem_to_u32(smem);
    int tid = threadIdx.x;
    int wid = tid >> 5;
    int lane = tid & 31;
    int row0 = blockIdx.x * 128;

    #pragma unroll
    for (int i = 0; i < 16; i++) {
        int slot = tid + i * 128;
        int r   = slot >> 4;
        int c16 = slot & 15;
        int ch  = c16 >> 3;
        int c8  = c16 & 7;
        int gr  = row0 + r;
        uint4 vh = make_uint4(0u, 0u, 0u, 0u), vl = vh;
        if (gr < NN) {
            size_t src = (size_t)gr * FH + ch * 64 + c8 * 8;
            vh = *(const uint4*)&g_r1h[src];
            vl = *(const uint4*)&g_r1l[src];
        }
        uint32_t off = SWZ((uint32_t)(r * 128 + c8 * 16));
        *(uint4*)(smem + G2_AH + ch * 16384 + off) = vh;
        *(uint4*)(smem + G2_AL + ch * 16384 + off) = vl;
    }
    for (int slot = tid; slot < FO * 16; slot += 128) {
        int r   = slot >> 4;
        int c16 = slot & 15;
        int ch  = c16 >> 3;
        int c8  = c16 & 7;
        size_t src = (size_t)r * FH + ch * 64 + c8 * 8;
        uint4 vh = *(const uint4*)&g_W2t_hi[src];
        uint4 vl = *(const uint4*)&g_W2t_lo[src];
        uint32_t off = SWZ((uint32_t)(r * 128 + c8 * 16));
        *(uint4*)(smem + G2_BH + ch * 5120 + off) = vh;
        *(uint4*)(smem + G2_BL + ch * 5120 + off) = vl;
    }
    __syncthreads();

    float acc[2][5][4] = {};
    int warp_m = wid * 32;
    int t = lane >> 3;

    #pragma unroll
    for (int pass = 0; pass < 3; pass++) {
        uint32_t baseA = (pass == 2) ? (uint32_t)G2_AL : (uint32_t)G2_AH;
        uint32_t baseB = (pass == 1) ? (uint32_t)G2_BL : (uint32_t)G2_BH;
        #pragma unroll
        for (int ch = 0; ch < 2; ch++) {
            uint32_t offA = baseA + ch * 16384u;
            uint32_t offB = baseB + ch * 5120u;
            #pragma unroll
            for (int ks = 0; ks < 4; ks++) {
                uint32_t afrag[2][4];
                #pragma unroll
                for (int mt = 0; mt < 2; mt++) {
                    int r  = warp_m + mt * 16 + ((t & 1) << 3) + (lane & 7);
                    int kk = ks * 16 + ((t >> 1) << 3);
                    ldsm_x4(afrag[mt], sb + offA + SWZ((uint32_t)(r * 128 + kk * 2)));
                }
                uint32_t bfrag[5][2];
                #pragma unroll
                for (int g = 0; g < 2; g++) {
                    int n  = g * 16 + ((t >> 1) << 3) + (lane & 7);
                    int kk = ks * 16 + ((t & 1) << 3);
                    uint32_t tmp[4];
                    ldsm_x4(tmp, sb + offB + SWZ((uint32_t)(n * 128 + kk * 2)));
                    bfrag[g * 2][0]     = tmp[0];
                    bfrag[g * 2][1]     = tmp[1];
                    bfrag[g * 2 + 1][0] = tmp[2];
                    bfrag[g * 2 + 1][1] = tmp[3];
                }
                {
                    int l  = lane & 15;
                    int n  = 32 + (l & 7);
                    int kk = ks * 16 + ((l >> 3) << 3);
                    uint32_t tmp2[2];
                    ldsm_x2(tmp2, sb + offB + SWZ((uint32_t)(n * 128 + kk * 2)));
                    bfrag[4][0] = tmp2[0];
                    bfrag[4][1] = tmp2[1];
                }
                #pragma unroll
                for (int mt = 0; mt < 2; mt++)
                    #pragma unroll
                    for (int nt = 0; nt < 5; nt++)
                        mma16816(acc[mt][nt], afrag[mt], bfrag[nt]);
            }
        }
    }

    #pragma unroll
    for (int mt = 0; mt < 2; mt++) {
        int m0 = row0 + warp_m + mt * 16 + (lane >> 2);
        #pragma unroll
        for (int nt = 0; nt < 5; nt++) {
            int n = nt * 8 + (lane & 3) * 2;
            if (m0 < NN)
                *(float2*)&g_h2[(size_t)m0 * FO + n] =
                    make_float2(acc[mt][nt][0], acc[mt][nt][1]);
            if (m0 + 8 < NN)
                *(float2*)&g_h2[(size_t)(m0 + 8) * FO + n] =
                    make_float2(acc[mt][nt][2], acc[mt][nt][3]);
        }
    }
}

// ---------------- layer-2 gather + b2 + log_softmax ----------------
__global__ void __launch_bounds__(256) k_gather2_softmax(
        const float* __restrict__ b2, float* __restrict__ out) {
    int node = (blockIdx.x * blockDim.x + threadIdx.x) >> 5;
    int lane = threadIdx.x & 31;
    if (node >= NN) return;

    int start = g_ptr[node];
    int cnt   = g_cnt[node];
    float s = g_dinv[node];
    s *= s;

    bool p0 = (lane < FO);
    bool p1 = (lane + 32 < FO);

    const float* self = &g_h2[(size_t)node * FO];
    float acc0 = p0 ? self[lane] * s : 0.f;
    float acc1 = p1 ? self[lane + 32] * s : 0.f;

    int i = 0;
    for (; i + 2 <= cnt; i += 2) {
        uint2 e0 = g_edges[start + i];
        uint2 e1 = g_edges[start + i + 1];
        float n0 = __uint_as_float(e0.y);
        float n1 = __uint_as_float(e1.y);
        const float* h0 = &g_h2[(size_t)e0.x * FO];
        const float* h1p = &g_h2[(size_t)e1.x * FO];
        if (p0) acc0 += h0[lane] * n0 + h1p[lane] * n1;
        if (p1) acc1 += h0[lane + 32] * n0 + h1p[lane + 32] * n1;
    }
    if (i < cnt) {
        uint2 e = g_edges[start + i];
        float nrm = __uint_as_float(e.y);
        const float* hr = &g_h2[(size_t)e.x * FO];
        if (p0) acc0 += hr[lane] * nrm;
        if (p1) acc1 += hr[lane + 32] * nrm;
    }

    float v0 = p0 ? acc0 + b2[lane] : -CUDART_INF_F;
    float v1 = p1 ? acc1 + b2[lane + 32] : -CUDART_INF_F;

    float m = fmaxf(v0, v1);
    #pragma unroll
    for (int o = 16; o; o >>= 1) m = fmaxf(m, __shfl_xor_sync(0xffffffffu, m, o));

    float sum = (p0 ? expf(v0 - m) : 0.f) + (p1 ? expf(v1 - m) : 0.f);
    #pragma unroll
    for (int o = 16; o; o >>= 1) sum += __shfl_xor_sync(0xffffffffu, sum, o);

    float lse = m + logf(sum);
    if (p0) out[(size_t)node * FO + lane]      = v0 - lse;
    if (p1) out[(size_t)node * FO + lane + 32] = v1 - lse;
}

// ---------------- launch ----------------
// Fork: GEMM1 runs on the main (capture) stream concurrently with the CSR
// build branch on g_ss.s2. Standard capture fork/join via events.
extern "C" void kernel_launch(void* const* d_in, const int* in_sizes, int n_in,
                              void* d_out, int out_size) {
    const float* x  = (const float*)d_in[0];
    const int*   ei = (const int*)d_in[1];
    const float* w  = (const float*)d_in[2];
    const float* W1 = (const float*)d_in[3];
    const float* b1 = (const float*)d_in[4];
    const float* W2 = (const float*)d_in[5];
    const float* b2 = (const float*)d_in[6];
    float* out = (float*)d_out;

    cudaFuncSetAttribute(k_gemm1_mma,
                         cudaFuncAttributeMaxDynamicSharedMemorySize, GEMM1_SMEM);
    cudaFuncSetAttribute(k_gemm2_mma,
                         cudaFuncAttributeMaxDynamicSharedMemorySize, GEMM2_SMEM);

    k_prep<<<(FIN * FH + 255) / 256, 256>>>(W1, W2);

    // fork CSR-build branch
    cudaEventRecord(g_ss.ev_fork, 0);
    cudaStreamWaitEvent(g_ss.s2, g_ss.ev_fork, 0);

    // main stream: GEMM1 (depends only on prep)
    k_gemm1_mma<<<(NN + 127) / 128, 256, GEMM1_SMEM>>>(x);

    // side stream: CSR build
    k_deg_hist<<<(NE + 255) / 256, 256, 0, g_ss.s2>>>(ei, w);
    k_scan1   <<<NB_SCAN, 256, 0, g_ss.s2>>>();
    k_scan2   <<<1, 256, 0, g_ss.s2>>>();
    k_scan3   <<<NB_SCAN, 256, 0, g_ss.s2>>>();
    k_fill    <<<(NE + 255) / 256, 256, 0, g_ss.s2>>>(ei, w);

    // join
    cudaEventRecord(g_ss.ev_join, g_ss.s2);
    cudaStreamWaitEvent(0, g_ss.ev_join, 0);

    k_gather1        <<<(NN * 32 + 255) / 256, 256>>>(b1);
    k_gemm2_mma      <<<(NN + 127) / 128, 128, GEMM2_SMEM>>>();
    k_gather2_softmax<<<(NN * 32 + 255) / 256, 256>>>(b2, out);
}

// round 17
// speedup vs baseline: 1.4229x; 1.0045x over previous
#include <cuda_runtime.h>
#include <cuda_bf16.h>
#include <math_constants.h>
#include <cstdint>

#define NN 50000
#define NE 800000
#define FIN 512
#define FH 128
#define FO 40

#define NB_SCAN ((NN + 255) / 256)   // 196

// ---------------- scratch (device globals: no allocation allowed) ----------
__device__ float g_dinv[NN];
__device__ int   g_cnt[NN];
__device__ int   g_ptr[NN];
__device__ int   g_cur[NN];
__device__ int   g_bsum[256];
__device__ uint2 g_edges[NE];              // packed (src, norm) sorted by dst
__device__ float g_h1[NN * FH];
__device__ float g_h2[NN * FO];
__device__ __nv_bfloat16 g_r1h[NN * FH];   // relu(a1+b1) hi
__device__ __nv_bfloat16 g_r1l[NN * FH];   // relu(a1+b1) lo
__device__ __nv_bfloat16 g_W1t_hi[FH * FIN];   // W1^T hi, [n][k]
__device__ __nv_bfloat16 g_W1t_lo[FH * FIN];   // W1^T lo
__device__ __nv_bfloat16 g_W2t_hi[FO * FH];    // W2^T hi, [n][k]
__device__ __nv_bfloat16 g_W2t_lo[FO * FH];    // W2^T lo

// ---- side stream + events, created once at program init -------------------
struct SideStream {
    cudaStream_t s2;
    cudaEvent_t ev_fork, ev_join;
    SideStream() {
        cudaStreamCreateWithFlags(&s2, cudaStreamNonBlocking);
        cudaEventCreateWithFlags(&ev_fork, cudaEventDisableTiming);
        cudaEventCreateWithFlags(&ev_join, cudaEventDisableTiming);
    }
};
static SideStream g_ss;

// ================= warp-MMA helpers (arch-neutral PTX, sm_80+) =============
__device__ __forceinline__ uint32_t smem_to_u32(const void* p) {
    uint32_t a;
    asm("{ .reg .u64 t; cvta.to.shared.u64 t, %1; cvt.u32.u64 %0, t; }"
        : "=r"(a) : "l"(p));
    return a;
}

__device__ __forceinline__ void ldsm_x4(uint32_t* r, uint32_t addr) {
    asm volatile("ldmatrix.sync.aligned.m8n8.x4.shared.b16 {%0,%1,%2,%3}, [%4];"
        : "=r"(r[0]), "=r"(r[1]), "=r"(r[2]), "=r"(r[3]) : "r"(addr));
}

__device__ __forceinline__ void ldsm_x2(uint32_t* r, uint32_t addr) {
    asm volatile("ldmatrix.sync.aligned.m8n8.x2.shared.b16 {%0,%1}, [%2];"
        : "=r"(r[0]), "=r"(r[1]) : "r"(addr));
}

__device__ __forceinline__ void mma16816(float* d, const uint32_t* a,
                                         const uint32_t* b) {
    asm volatile("mma.sync.aligned.m16n8k16.row.col.f32.bf16.bf16.f32 "
        "{%0,%1,%2,%3}, {%4,%5,%6,%7}, {%8,%9}, {%0,%1,%2,%3};"
        : "+f"(d[0]), "+f"(d[1]), "+f"(d[2]), "+f"(d[3])
        : "r"(a[0]), "r"(a[1]), "r"(a[2]), "r"(a[3]), "r"(b[0]), "r"(b[1]));
}

#define CP_ASYNC16(dst, src) \
    asm volatile("cp.async.cg.shared.global [%0], [%1], 16;" \
        :: "r"(dst), "l"(src) : "memory")
#define CP_COMMIT() asm volatile("cp.async.commit_group;" ::: "memory")

#define SWZ(off) ((off) ^ (((off) >> 3) & 0x70))

// ---------------- fused init: dinv/cnt reset + W1 & W2 splits --------------
__global__ void k_prep(const float* __restrict__ W1,
                       const float* __restrict__ W2) {
    int i = blockIdx.x * blockDim.x + threadIdx.x;
    if (i < NN) { g_dinv[i] = 1.0f; g_cnt[i] = 0; }
    if (i < FIN * FH) {
        int k = i >> 7, n = i & 127;
        float v = W1[i];
        __nv_bfloat16 h = __float2bfloat16(v);
        g_W1t_hi[n * FIN + k] = h;
        g_W1t_lo[n * FIN + k] = __float2bfloat16(v - __bfloat162float(h));
    }
    if (i < FH * FO) {
        int k = i / FO, n = i % FO;
        float v = W2[i];
        __nv_bfloat16 h = __float2bfloat16(v);
        g_W2t_hi[n * FH + k] = h;
        g_W2t_lo[n * FH + k] = __float2bfloat16(v - __bfloat162float(h));
    }
}

__global__ void k_deg_hist(const int* __restrict__ ei, const float* __restrict__ w) {
    int e = blockIdx.x * blockDim.x + threadIdx.x;
    if (e < NE) {
        int c = ei[NE + e];
        atomicAdd(&g_dinv[c], w[e]);
        atomicAdd(&g_cnt[c], 1);
    }
}

// ---------------- 3-kernel exclusive scan (scan1 fuses dinv finalize) ------
__global__ void k_scan1() {
    __shared__ int sh[256];
    int tid = threadIdx.x;
    int i = blockIdx.x * 256 + tid;
    int v = (i < NN) ? g_cnt[i] : 0;
    if (i < NN) g_dinv[i] = rsqrtf(g_dinv[i]);   // deg >= 1 always
    sh[tid] = v;
    __syncthreads();
    #pragma unroll
    for (int o = 1; o < 256; o <<= 1) {
        int t = (tid >= o) ? sh[tid - o] : 0;
        __syncthreads();
        sh[tid] += t;
        __syncthreads();
    }
    if (i < NN) g_ptr[i] = sh[tid] - v;
    if (tid == 255) g_bsum[blockIdx.x] = sh[255];
}

__global__ void k_scan2() {
    __shared__ int sh[256];
    int tid = threadIdx.x;
    int v = (tid < NB_SCAN) ? g_bsum[tid] : 0;
    sh[tid] = v;
    __syncthreads();
    #pragma unroll
    for (int o = 1; o < 256; o <<= 1) {
        int t = (tid >= o) ? sh[tid - o] : 0;
        __syncthreads();
        sh[tid] += t;
        __syncthreads();
    }
    if (tid < NB_SCAN) g_bsum[tid] = sh[tid] - v;
}

__global__ void k_scan3() {
    int i = blockIdx.x * blockDim.x + threadIdx.x;
    if (i < NN) {
        int p = g_ptr[i] + g_bsum[i >> 8];
        g_ptr[i] = p;
        g_cur[i] = p;
    }
}

__global__ void k_fill(const int* __restrict__ ei, const float* __restrict__ w) {
    int e = blockIdx.x * blockDim.x + threadIdx.x;
    if (e < NE) {
        int r = ei[e];
        int c = ei[NE + e];
        float nrm = g_dinv[r] * w[e] * g_dinv[c];
        int pos = atomicAdd(&g_cur[c], 1);
        g_edges[pos] = make_uint2((unsigned)r, __float_as_uint(nrm));
    }
}

// ---------------- GEMM1 (mma.sync 3xBF16, pipelined): h1 = x @ W1 ----------
// Fragment-reuse inner loop (R16 win): load A_hi/A_lo/B_hi/B_lo once per
// k-step, issue all three products.
#define OFF_AH 0
#define OFF_AL 16384
#define OFF_B  32768
#define GEMM1_SMEM 98304

__global__ void __launch_bounds__(256) k_gemm1_mma(const float* __restrict__ A) {
    extern __shared__ char smem[];
    uint32_t sb = smem_to_u32(smem);
    int tid = threadIdx.x;
    int wid = tid >> 5;
    int lane = tid & 31;
    int row0 = blockIdx.x * 128;
    int warp_m = (wid & 3) * 32;
    int warp_n = (wid >> 2) * 64;

    float acc[2][8][4] = {};
    float4 areg[8];

    {
        uint32_t bb = sb + OFF_B;
        #pragma unroll
        for (int i = 0; i < 4; i++) {
            int slot = tid + i * 256;
            int r  = slot >> 3;
            int c8 = slot & 7;
            size_t src = (size_t)r * FIN + c8 * 8;
            uint32_t off = SWZ((uint32_t)(r * 128 + c8 * 16));
            CP_ASYNC16(bb + off,          (const void*)&g_W1t_hi[src]);
            CP_ASYNC16(bb + 16384 + off,  (const void*)&g_W1t_lo[src]);
        }
        CP_COMMIT();
        #pragma unroll
        for (int i = 0; i < 8; i++) {
            int slot = tid + i * 256;
            int r  = slot >> 4;
            int c4 = slot & 15;
            int gr = row0 + r;
            areg[i] = make_float4(0.f, 0.f, 0.f, 0.f);
            if (gr < NN) areg[i] = *(const float4*)&A[(size_t)gr * FIN + c4 * 4];
        }
    }

    for (int c = 0; c < 8; c++) {
        #pragma unroll
        for (int i = 0; i < 8; i++) {
            int slot = tid + i * 256;
            int r  = slot >> 4;
            int c4 = slot & 15;
            float4 v = areg[i];
            __nv_bfloat162 h01 = __floats2bfloat162_rn(v.x, v.y);
            __nv_bfloat162 h23 = __floats2bfloat162_rn(v.z, v.w);
            float2 hf01 = __bfloat1622float2(h01);
            float2 hf23 = __bfloat1622float2(h23);
            __nv_bfloat162 l01 = __floats2bfloat162_rn(v.x - hf01.x, v.y - hf01.y);
            __nv_bfloat162 l23 = __floats2bfloat162_rn(v.z - hf23.x, v.w - hf23.y);
            uint32_t off = SWZ((uint32_t)(r * 128 + c4 * 8));
            *(uint2*)(smem + OFF_AH + off) =
                make_uint2(*(uint32_t*)&h01, *(uint32_t*)&h23);
            *(uint2*)(smem + OFF_AL + off) =
                make_uint2(*(uint32_t*)&l01, *(uint32_t*)&l23);
        }

        if (c < 7) {
            int k1 = (c + 1) * 64;
            uint32_t bb = sb + OFF_B + ((c + 1) & 1) * 32768;
            #pragma unroll
            for (int i = 0; i < 4; i++) {
                int slot = tid + i * 256;
                int r  = slot >> 3;
                int c8 = slot & 7;
                size_t src = (size_t)r * FIN + k1 + c8 * 8;
                uint32_t off = SWZ((uint32_t)(r * 128 + c8 * 16));
                CP_ASYNC16(bb + off,         (const void*)&g_W1t_hi[src]);
                CP_ASYNC16(bb + 16384 + off, (const void*)&g_W1t_lo[src]);
            }
            CP_COMMIT();
            #pragma unroll
            for (int i = 0; i < 8; i++) {
                int slot = tid + i * 256;
                int r  = slot >> 4;
                int c4 = slot & 15;
                int gr = row0 + r;
                areg[i] = make_float4(0.f, 0.f, 0.f, 0.f);
                if (gr < NN)
                    areg[i] = *(const float4*)&A[(size_t)gr * FIN + k1 + c4 * 4];
            }
            asm volatile("cp.async.wait_group 1;" ::: "memory");
        } else {
            asm volatile("cp.async.wait_group 0;" ::: "memory");
        }
        __syncthreads();

        uint32_t offBH = (uint32_t)OFF_B + (c & 1) * 32768u;
        uint32_t offBL = offBH + 16384u;
        #pragma unroll
        for (int ks = 0; ks < 4; ks++) {
            int t = lane >> 3;
            int ar = ((t & 1) << 3) + (lane & 7);
            int ak = ks * 16 + ((t >> 1) << 3);
            int bn = ((t >> 1) << 3) + (lane & 7);
            int bk = ks * 16 + ((t & 1) << 3);

            uint32_t afH[2][4], afL[2][4];
            #pragma unroll
            for (int mt = 0; mt < 2; mt++) {
                uint32_t o = SWZ((uint32_t)((warp_m + mt * 16 + ar) * 128 + ak * 2));
                ldsm_x4(afH[mt], sb + OFF_AH + o);
                ldsm_x4(afL[mt], sb + OFF_AL + o);
            }
            uint32_t bfH[8][2], bfL[8][2];
            #pragma unroll
            for (int nt2 = 0; nt2 < 4; nt2++) {
                uint32_t o = SWZ((uint32_t)((warp_n + nt2 * 16 + bn) * 128 + bk * 2));
                uint32_t tmp[4];
                ldsm_x4(tmp, sb + offBH + o);
                bfH[nt2 * 2][0]     = tmp[0];
                bfH[nt2 * 2][1]     = tmp[1];
                bfH[nt2 * 2 + 1][0] = tmp[2];
                bfH[nt2 * 2 + 1][1] = tmp[3];
                ldsm_x4(tmp, sb + offBL + o);
                bfL[nt2 * 2][0]     = tmp[0];
                bfL[nt2 * 2][1]     = tmp[1];
                bfL[nt2 * 2 + 1][0] = tmp[2];
                bfL[nt2 * 2 + 1][1] = tmp[3];
            }

            #pragma unroll
            for (int mt = 0; mt < 2; mt++)
                #pragma unroll
                for (int nt = 0; nt < 8; nt++)
                    mma16816(acc[mt][nt], afH[mt], bfH[nt]);
            #pragma unroll
            for (int mt = 0; mt < 2; mt++)
                #pragma unroll
                for (int nt = 0; nt < 8; nt++)
                    mma16816(acc[mt][nt], afH[mt], bfL[nt]);
            #pragma unroll
            for (int mt = 0; mt < 2; mt++)
                #pragma unroll
                for (int nt = 0; nt < 8; nt++)
                    mma16816(acc[mt][nt], afL[mt], bfH[nt]);
        }
        __syncthreads();
    }

    #pragma unroll
    for (int mt = 0; mt < 2; mt++) {
        int m0 = row0 + warp_m + mt * 16 + (lane >> 2);
        #pragma unroll
        for (int nt = 0; nt < 8; nt++) {
            int n = warp_n + nt * 8 + (lane & 3) * 2;
            if (m0 < NN)
                *(float2*)&g_h1[(size_t)m0 * FH + n] =
                    make_float2(acc[mt][nt][0], acc[mt][nt][1]);
            if (m0 + 8 < NN)
                *(float2*)&g_h1[(size_t)(m0 + 8) * FH + n] =
                    make_float2(acc[mt][nt][2], acc[mt][nt][3]);
        }
    }
}

// ------- layer-1 gather + bias + relu + bf16 hi/lo split (fused) ----------
__global__ void __launch_bounds__(256) k_gather1(const float* __restrict__ b1) {
    int node = (blockIdx.x * blockDim.x + threadIdx.x) >> 5;
    int lane = threadIdx.x & 31;
    if (node >= NN) return;

    int start = g_ptr[node];
    int cnt   = g_cnt[node];
    float s = g_dinv[node];
    s *= s;

    float4 acc = *(const float4*)&g_h1[(size_t)node * FH + lane * 4];
    acc.x *= s; acc.y *= s; acc.z *= s; acc.w *= s;

    int i = 0;
    for (; i + 4 <= cnt; i += 4) {
        uint2 e0 = g_edges[start + i];
        uint2 e1 = g_edges[start + i + 1];
        uint2 e2 = g_edges[start + i + 2];
        uint2 e3 = g_edges[start + i + 3];
        float n0 = __uint_as_float(e0.y);
        float n1 = __uint_as_float(e1.y);
        float n2 = __uint_as_float(e2.y);
        float n3 = __uint_as_float(e3.y);
        float4 v0 = *(const float4*)&g_h1[(size_t)e0.x * FH + lane * 4];
        float4 v1 = *(const float4*)&g_h1[(size_t)e1.x * FH + lane * 4];
        float4 v2 = *(const float4*)&g_h1[(size_t)e2.x * FH + lane * 4];
        float4 v3 = *(const float4*)&g_h1[(size_t)e3.x * FH + lane * 4];
        acc.x += v0.x * n0 + v1.x * n1 + v2.x * n2 + v3.x * n3;
        acc.y += v0.y * n0 + v1.y * n1 + v2.y * n2 + v3.y * n3;
        acc.z += v0.z * n0 + v1.z * n1 + v2.z * n2 + v3.z * n3;
        acc.w += v0.w * n0 + v1.w * n1 + v2.w * n2 + v3.w * n3;
    }
    for (; i < cnt; i++) {
        uint2 e0 = g_edges[start + i];
        float n0 = __uint_as_float(e0.y);
        float4 v0 = *(const float4*)&g_h1[(size_t)e0.x * FH + lane * 4];
        acc.x += v0.x * n0;
        acc.y += v0.y * n0;
        acc.z += v0.z * n0;
        acc.w += v0.w * n0;
    }

    float4 bv = *(const float4*)&b1[lane * 4];
    acc.x = fmaxf(acc.x + bv.x, 0.f);
    acc.y = fmaxf(acc.y + bv.y, 0.f);
    acc.z = fmaxf(acc.z + bv.z, 0.f);
    acc.w = fmaxf(acc.w + bv.w, 0.f);
    __nv_bfloat162 h01 = __floats2bfloat162_rn(acc.x, acc.y);
    __nv_bfloat162 h23 = __floats2bfloat162_rn(acc.z, acc.w);
    float2 hf01 = __bfloat1622float2(h01);
    float2 hf23 = __bfloat1622float2(h23);
    __nv_bfloat162 l01 = __floats2bfloat162_rn(acc.x - hf01.x, acc.y - hf01.y);
    __nv_bfloat162 l23 = __floats2bfloat162_rn(acc.z - hf23.x, acc.w - hf23.y);
    size_t dst = (size_t)node * FH + lane * 4;
    *(uint2*)&g_r1h[dst] = make_uint2(*(uint32_t*)&h01, *(uint32_t*)&h23);
    *(uint2*)&g_r1l[dst] = make_uint2(*(uint32_t*)&l01, *(uint32_t*)&l23);
}

// ---------------- GEMM2 (mma.sync 3xBF16, fragment reuse): h2 = r1 @ W2 ----
#define G2_AH 0
#define G2_AL 32768
#define G2_BH 65536
#define G2_BL 75776
#define GEMM2_SMEM 86016

__global__ void __launch_bounds__(128) k_gemm2_mma() {
    extern __shared__ char smem[];
    uint32_t sb = smem_to_u32(smem);
    int tid = threadIdx.x;
    int wid = tid >> 5;
    int lane = tid & 31;
    int row0 = blockIdx.x * 128;

    #pragma unroll
    for (int i = 0; i < 16; i++) {
        int slot = tid + i * 128;
        int r   = slot >> 4;
        int c16 = slot & 15;
        int ch  = c16 >> 3;
        int c8  = c16 & 7;
        int gr  = row0 + r;
        uint4 vh = make_uint4(0u, 0u, 0u, 0u), vl = vh;
        if (gr < NN) {
            size_t src = (size_t)gr * FH + ch * 64 + c8 * 8;
            vh = *(const uint4*)&g_r1h[src];
            vl = *(const uint4*)&g_r1l[src];
        }
        uint32_t off = SWZ((uint32_t)(r * 128 + c8 * 16));
        *(uint4*)(smem + G2_AH + ch * 16384 + off) = vh;
        *(uint4*)(smem + G2_AL + ch * 16384 + off) = vl;
    }
    for (int slot = tid; slot < FO * 16; slot += 128) {
        int r   = slot >> 4;
        int c16 = slot & 15;
        int ch  = c16 >> 3;
        int c8  = c16 & 7;
        size_t src = (size_t)r * FH + ch * 64 + c8 * 8;
        uint4 vh = *(const uint4*)&g_W2t_hi[src];
        uint4 vl = *(const uint4*)&g_W2t_lo[src];
        uint32_t off = SWZ((uint32_t)(r * 128 + c8 * 16));
        *(uint4*)(smem + G2_BH + ch * 5120 + off) = vh;
        *(uint4*)(smem + G2_BL + ch * 5120 + off) = vl;
    }
    __syncthreads();

    float acc[2][5][4] = {};
    int warp_m = wid * 32;
    int t = lane >> 3;

    #pragma unroll
    for (int ch = 0; ch < 2; ch++) {
        uint32_t oAH = (uint32_t)G2_AH + ch * 16384u;
        uint32_t oAL = (uint32_t)G2_AL + ch * 16384u;
        uint32_t oBH = (uint32_t)G2_BH + ch * 5120u;
        uint32_t oBL = (uint32_t)G2_BL + ch * 5120u;
        #pragma unroll
        for (int ks = 0; ks < 4; ks++) {
            int ar = ((t & 1) << 3) + (lane & 7);
            int ak = ks * 16 + ((t >> 1) << 3);
            int bn = ((t >> 1) << 3) + (lane & 7);
            int bk = ks * 16 + ((t & 1) << 3);

            // A fragments (hi, lo) once
            uint32_t afH[2][4], afL[2][4];
            #pragma unroll
            for (int mt = 0; mt < 2; mt++) {
                uint32_t o = SWZ((uint32_t)((warp_m + mt * 16 + ar) * 128 + ak * 2));
                ldsm_x4(afH[mt], sb + oAH + o);
                ldsm_x4(afL[mt], sb + oAL + o);
            }
            // B fragments (hi, lo) once: n-tiles 0..3 via x4, tail tile 4 via x2
            uint32_t bfH[5][2], bfL[5][2];
            #pragma unroll
            for (int g = 0; g < 2; g++) {
                uint32_t o = SWZ((uint32_t)((g * 16 + bn) * 128 + bk * 2));
                uint32_t tmp[4];
                ldsm_x4(tmp, sb + oBH + o);
                bfH[g * 2][0]     = tmp[0];
                bfH[g * 2][1]     = tmp[1];
                bfH[g * 2 + 1][0] = tmp[2];
                bfH[g * 2 + 1][1] = tmp[3];
                ldsm_x4(tmp, sb + oBL + o);
                bfL[g * 2][0]     = tmp[0];
                bfL[g * 2][1]     = tmp[1];
                bfL[g * 2 + 1][0] = tmp[2];
                bfL[g * 2 + 1][1] = tmp[3];
            }
            {
                int l  = lane & 15;
                uint32_t o = SWZ((uint32_t)((32 + (l & 7)) * 128 +
                                            (ks * 16 + ((l >> 3) << 3)) * 2));
                ldsm_x2(bfH[4], sb + oBH + o);
                ldsm_x2(bfL[4], sb + oBL + o);
            }

            #pragma unroll
            for (int mt = 0; mt < 2; mt++)
                #pragma unroll
                for (int nt = 0; nt < 5; nt++)
                    mma16816(acc[mt][nt], afH[mt], bfH[nt]);
            #pragma unroll
            for (int mt = 0; mt < 2; mt++)
                #pragma unroll
                for (int nt = 0; nt < 5; nt++)
                    mma16816(acc[mt][nt], afH[mt], bfL[nt]);
            #pragma unroll
            for (int mt = 0; mt < 2; mt++)
                #pragma unroll
                for (int nt = 0; nt < 5; nt++)
                    mma16816(acc[mt][nt], afL[mt], bfH[nt]);
        }
    }

    #pragma unroll
    for (int mt = 0; mt < 2; mt++) {
        int m0 = row0 + warp_m + mt * 16 + (lane >> 2);
        #pragma unroll
        for (int nt = 0; nt < 5; nt++) {
            int n = nt * 8 + (lane & 3) * 2;
            if (m0 < NN)
                *(float2*)&g_h2[(size_t)m0 * FO + n] =
                    make_float2(acc[mt][nt][0], acc[mt][nt][1]);
            if (m0 + 8 < NN)
                *(float2*)&g_h2[(size_t)(m0 + 8) * FO + n] =
                    make_float2(acc[mt][nt][2], acc[mt][nt][3]);
        }
    }
}

// ---------------- layer-2 gather + b2 + log_softmax ----------------
__global__ void __launch_bounds__(256) k_gather2_softmax(
        const float* __restrict__ b2, float* __restrict__ out) {
    int node = (blockIdx.x * blockDim.x + threadIdx.x) >> 5;
    int lane = threadIdx.x & 31;
    if (node >= NN) return;

    int start = g_ptr[node];
    int cnt   = g_cnt[node];
    float s = g_dinv[node];
    s *= s;

    bool p0 = (lane < FO);
    bool p1 = (lane + 32 < FO);

    const float* self = &g_h2[(size_t)node * FO];
    float acc0 = p0 ? self[lane] * s : 0.f;
    float acc1 = p1 ? self[lane + 32] * s : 0.f;

    int i = 0;
    for (; i + 2 <= cnt; i += 2) {
        uint2 e0 = g_edges[start + i];
        uint2 e1 = g_edges[start + i + 1];
        float n0 = __uint_as_float(e0.y);
        float n1 = __uint_as_float(e1.y);
        const float* h0 = &g_h2[(size_t)e0.x * FO];
        const float* h1p = &g_h2[(size_t)e1.x * FO];
        if (p0) acc0 += h0[lane] * n0 + h1p[lane] * n1;
        if (p1) acc1 += h0[lane + 32] * n0 + h1p[lane + 32] * n1;
    }
    if (i < cnt) {
        uint2 e = g_edges[start + i];
        float nrm = __uint_as_float(e.y);
        const float* hr = &g_h2[(size_t)e.x * FO];
        if (p0) acc0 += hr[lane] * nrm;
        if (p1) acc1 += hr[lane + 32] * nrm;
    }

    float v0 = p0 ? acc0 + b2[lane] : -CUDART_INF_F;
    float v1 = p1 ? acc1 + b2[lane + 32] : -CUDART_INF_F;

    float m = fmaxf(v0, v1);
    #pragma unroll
    for (int o = 16; o; o >>= 1) m = fmaxf(m, __shfl_xor_sync(0xffffffffu, m, o));

    float sum = (p0 ? expf(v0 - m) : 0.f) + (p1 ? expf(v1 - m) : 0.f);
    #pragma unroll
    for (int o = 16; o; o >>= 1) sum += __shfl_xor_sync(0xffffffffu, sum, o);

    float lse = m + logf(sum);
    if (p0) out[(size_t)node * FO + lane]      = v0 - lse;
    if (p1) out[(size_t)node * FO + lane + 32] = v1 - lse;
}

// ---------------- launch ----------------
extern "C" void kernel_launch(void* const* d_in, const int* in_sizes, int n_in,
                              void* d_out, int out_size) {
    const float* x  = (const float*)d_in[0];
    const int*   ei = (const int*)d_in[1];
    const float* w  = (const float*)d_in[2];
    const float* W1 = (const float*)d_in[3];
    const float* b1 = (const float*)d_in[4];
    const float* W2 = (const float*)d_in[5];
    const float* b2 = (const float*)d_in[6];
    float* out = (float*)d_out;

    cudaFuncSetAttribute(k_gemm1_mma,
                         cudaFuncAttributeMaxDynamicSharedMemorySize, GEMM1_SMEM);
    cudaFuncSetAttribute(k_gemm2_mma,
                         cudaFuncAttributeMaxDynamicSharedMemorySize, GEMM2_SMEM);

    k_prep<<<(FIN * FH + 255) / 256, 256>>>(W1, W2);

    // fork CSR-build branch
    cudaEventRecord(g_ss.ev_fork, 0);
    cudaStreamWaitEvent(g_ss.s2, g_ss.ev_fork, 0);

    // main stream: GEMM1 (depends only on prep)
    k_gemm1_mma<<<(NN + 127) / 128, 256, GEMM1_SMEM>>>(x);

    // side stream: CSR build
    k_deg_hist<<<(NE + 255) / 256, 256, 0, g_ss.s2>>>(ei, w);
    k_scan1   <<<NB_SCAN, 256, 0, g_ss.s2>>>();
    k_scan2   <<<1, 256, 0, g_ss.s2>>>();
    k_scan3   <<<NB_SCAN, 256, 0, g_ss.s2>>>();
    k_fill    <<<(NE + 255) / 256, 256, 0, g_ss.s2>>>(ei, w);

    // join
    cudaEventRecord(g_ss.ev_join, g_ss.s2);
    cudaStreamWaitEvent(0, g_ss.ev_join, 0);

    k_gather1        <<<(NN * 32 + 255) / 256, 256>>>(b1);
    k_gemm2_mma      <<<(NN + 127) / 128, 128, GEMM2_SMEM>>>();
    k_gather2_softmax<<<(NN * 32 + 255) / 256, 256>>>(b2, out);
}